// round 1
// baseline (speedup 1.0000x reference)
#include <cuda_runtime.h>
#include <cstdint>
#include <cstdio>

// ---------------------------------------------------------------------------
// TrivialTreeTagger: B=32768 elements, 5 tree-LSTM blocks (H=64,E=32) each.
// Key insight: last = relu(h3) * (s==4)  =>  only s==4 elements (~25%) need
// LSTM work; rest collapse to relu(Wc[:, :32] @ emb[x0] + bc) -> Wt -> lsm.
// ---------------------------------------------------------------------------

#define MAXB 32768

__device__ int g_count;
__device__ int g_idx[MAXB];

__device__ __forceinline__ float fsig(float x) {
    return __fdividef(1.0f, 1.0f + __expf(-x));
}
__device__ __forceinline__ float ftanh_(float x) {
    return __fdividef(2.0f, 1.0f + __expf(-2.0f * x)) - 1.0f;
}

__device__ __forceinline__ void load32(float (&dst)[32], const float* __restrict__ src) {
    const float4* p = reinterpret_cast<const float4*>(src);
#pragma unroll
    for (int c = 0; c < 8; ++c) {
        float4 v = p[c];
        dst[4 * c + 0] = v.x; dst[4 * c + 1] = v.y;
        dst[4 * c + 2] = v.z; dst[4 * c + 3] = v.w;
    }
}

// -------------------- kernel 0: reset compaction counter --------------------
__global__ void k_zero() { g_count = 0; }

// -------------------- kernel 1: trivial path + compaction -------------------
// One thread per element. s!=4: full trivial output. s==4: append to list.
__global__ void __launch_bounds__(256) k_trivial(
    const int* __restrict__ x, const int* __restrict__ s,
    const float* __restrict__ emb,
    const float* __restrict__ Wc, const float* __restrict__ bcv,
    const float* __restrict__ Wt, const float* __restrict__ btv,
    float* __restrict__ out, int B)
{
    int i = blockIdx.x * 256 + threadIdx.x;
    bool valid = i < B;
    bool act = valid && (s[i] == 4);
    unsigned bal = __ballot_sync(0xffffffffu, act);
    if (act) {
        int lane = threadIdx.x & 31;
        int leader = __ffs(bal) - 1;
        int pos = 0;
        if (lane == leader) pos = atomicAdd(&g_count, __popc(bal));
        pos = __shfl_sync(bal, pos, leader);
        pos += __popc(bal & ((1u << lane) - 1));
        g_idx[pos] = i;
    } else if (valid) {
        float r[32];
        load32(r, emb + (size_t)x[i * 16] * 32);
        float cb[32];
#pragma unroll
        for (int m = 0; m < 32; ++m) {
            float acc = bcv[m];
            const float4* w = reinterpret_cast<const float4*>(Wc + m * 96);
#pragma unroll
            for (int k = 0; k < 8; ++k) {
                float4 wv = w[k];
                acc = fmaf(wv.x, r[4 * k + 0], acc);
                acc = fmaf(wv.y, r[4 * k + 1], acc);
                acc = fmaf(wv.z, r[4 * k + 2], acc);
                acc = fmaf(wv.w, r[4 * k + 3], acc);
            }
            cb[m] = fmaxf(acc, 0.0f);
        }
        float lg[64];
        float mx = -1e30f;
#pragma unroll
        for (int m = 0; m < 64; ++m) {
            float acc = btv[m];
            const float4* w = reinterpret_cast<const float4*>(Wt + m * 32);
#pragma unroll
            for (int k = 0; k < 8; ++k) {
                float4 wv = w[k];
                acc = fmaf(wv.x, cb[4 * k + 0], acc);
                acc = fmaf(wv.y, cb[4 * k + 1], acc);
                acc = fmaf(wv.z, cb[4 * k + 2], acc);
                acc = fmaf(wv.w, cb[4 * k + 3], acc);
            }
            lg[m] = acc;
            mx = fmaxf(mx, acc);
        }
        float se = 0.0f;
#pragma unroll
        for (int m = 0; m < 64; ++m) se += __expf(lg[m] - mx);
        float lse = mx + logf(se);
        float4* o4 = reinterpret_cast<float4*>(out + (size_t)i * 64);
#pragma unroll
        for (int c = 0; c < 16; ++c) {
            float4 v;
            v.x = lg[4 * c + 0] - lse; v.y = lg[4 * c + 1] - lse;
            v.z = lg[4 * c + 2] - lse; v.w = lg[4 * c + 3] - lse;
            o4[c] = v;
        }
    }
}

// -------------------- kernel 2: active-element LSTM pipeline ----------------
// 4 threads per element (16 hidden units each), 256 thr/block = 64 elem/block.
// Weights in shared, gate-quad float4 layout -> broadcast LDS (1 per 4 FFMA).
struct SmemB {
    float4 W4[96 * 64];   // [k][j]: rows (j, 64+j, 128+j, 192+j), col k (0..31=Wih, 32..95=Whh)
    float4 b4[64];        // bih+bhh gate quads
    float4 a04[64];       // b4 + Whh@h0 quads (step-0 constant)
    float  c0s[64];
    float  Wc[32 * 96];
    float  bc[32];
    float  Wt[64 * 32];
    float  bt[64];
    float  hstage[64 * 65];   // [j][e], stride 65
    float  cstage[64 * 65];   // per-element cell state
    float  hid[4 * 32 * 64];  // hidden[0..3] combs: [bp][comp][e]
};

__global__ void __launch_bounds__(256, 1) k_lstm(
    const int* __restrict__ x, const float* __restrict__ emb,
    const float* __restrict__ Wih, const float* __restrict__ Whh,
    const float* __restrict__ bih, const float* __restrict__ bhh,
    const float* __restrict__ h0, const float* __restrict__ c0,
    const float* __restrict__ Wc, const float* __restrict__ bcv,
    const float* __restrict__ Wt, const float* __restrict__ btv,
    float* __restrict__ out)
{
    int cnt = g_count;
    if (blockIdx.x * 64 >= cnt) return;

    extern __shared__ char smraw[];
    SmemB* sm = reinterpret_cast<SmemB*>(smraw);
    int tid = threadIdx.x;

    // ---- shared init ----
    for (int n = tid; n < 96 * 64; n += 256) {
        int k = n >> 6, j = n & 63;
        float4 w;
        if (k < 32) {
            w.x = Wih[j * 32 + k];          w.y = Wih[(64 + j) * 32 + k];
            w.z = Wih[(128 + j) * 32 + k];  w.w = Wih[(192 + j) * 32 + k];
        } else {
            int kk = k - 32;
            w.x = Whh[j * 64 + kk];         w.y = Whh[(64 + j) * 64 + kk];
            w.z = Whh[(128 + j) * 64 + kk]; w.w = Whh[(192 + j) * 64 + kk];
        }
        sm->W4[n] = w;
    }
    if (tid < 64) {
        int j = tid;
        float4 bb;
        bb.x = bih[j] + bhh[j];
        bb.y = bih[64 + j] + bhh[64 + j];
        bb.z = bih[128 + j] + bhh[128 + j];
        bb.w = bih[192 + j] + bhh[192 + j];
        sm->b4[j] = bb;
        float4 aa = bb;
        for (int k = 0; k < 64; ++k) {
            float hk = h0[k];
            aa.x = fmaf(Whh[j * 64 + k], hk, aa.x);
            aa.y = fmaf(Whh[(64 + j) * 64 + k], hk, aa.y);
            aa.z = fmaf(Whh[(128 + j) * 64 + k], hk, aa.z);
            aa.w = fmaf(Whh[(192 + j) * 64 + k], hk, aa.w);
        }
        sm->a04[j] = aa;
        sm->c0s[j] = c0[j];
        sm->bt[j] = btv[j];
    }
    for (int n = tid; n < 32 * 96; n += 256) sm->Wc[n] = Wc[n];
    if (tid < 32) sm->bc[tid] = bcv[tid];
    for (int n = tid; n < 64 * 32; n += 256) sm->Wt[n] = Wt[n];
    __syncthreads();

    int g = blockIdx.x * 64 + (tid >> 2);
    int q = tid & 3;              // which 16-slice of H this thread owns
    int e = (tid >> 2) & 63;      // element slot within block
    int warp_first_g = blockIdx.x * 64 + ((tid >> 5) << 3);
    if (warp_first_g >= cnt) return;   // whole warp beyond count
    bool act = g < cnt;
    int i = g_idx[act ? g : (cnt - 1)];
    const int* xr = x + i * 16;

    float h[64], xt[32];

    for (int bp = 0; bp < 5; ++bp) {
        // ---- step 0 (uses precomputed a0 = Whh@h0 + b) ----
        if (bp < 4) {
            load32(xt, emb + (size_t)xr[4 * bp] * 32);
        } else {
#pragma unroll
            for (int c = 0; c < 32; ++c) xt[c] = sm->hid[c * 64 + e];
        }
        for (int jj = 0; jj < 16; ++jj) {
            int j = (q << 4) + jj;
            const float4* wp = sm->W4 + j;
            float4 acc = sm->a04[j];
#pragma unroll
            for (int k = 0; k < 32; ++k) {
                float4 w = wp[k * 64];
                acc.x = fmaf(w.x, xt[k], acc.x); acc.y = fmaf(w.y, xt[k], acc.y);
                acc.z = fmaf(w.z, xt[k], acc.z); acc.w = fmaf(w.w, xt[k], acc.w);
            }
            float ig = fsig(acc.x), fg = fsig(acc.y);
            float gv = ftanh_(acc.z), og = fsig(acc.w);
            float cc = fmaf(fg, sm->c0s[j], ig * gv);
            sm->cstage[j * 65 + e] = cc;
            sm->hstage[j * 65 + e] = og * ftanh_(cc);
        }
        __syncwarp();
#pragma unroll
        for (int k = 0; k < 64; ++k) h[k] = sm->hstage[k * 65 + e];
        __syncwarp();

        // ---- steps 1..3 ----
        for (int t = 1; t < 4; ++t) {
            if (bp < 4) {
                load32(xt, emb + (size_t)xr[4 * bp + t] * 32);
            } else {
#pragma unroll
                for (int c = 0; c < 32; ++c) xt[c] = sm->hid[(t * 32 + c) * 64 + e];
            }
            for (int jj = 0; jj < 16; ++jj) {
                int j = (q << 4) + jj;
                const float4* wp = sm->W4 + j;
                float4 acc = sm->b4[j];
#pragma unroll
                for (int k = 0; k < 32; ++k) {
                    float4 w = wp[k * 64];
                    acc.x = fmaf(w.x, xt[k], acc.x); acc.y = fmaf(w.y, xt[k], acc.y);
                    acc.z = fmaf(w.z, xt[k], acc.z); acc.w = fmaf(w.w, xt[k], acc.w);
                }
#pragma unroll
                for (int k = 0; k < 64; ++k) {
                    float4 w = wp[(32 + k) * 64];
                    acc.x = fmaf(w.x, h[k], acc.x); acc.y = fmaf(w.y, h[k], acc.y);
                    acc.z = fmaf(w.z, h[k], acc.z); acc.w = fmaf(w.w, h[k], acc.w);
                }
                float ig = fsig(acc.x), fg = fsig(acc.y);
                float gv = ftanh_(acc.z), og = fsig(acc.w);
                float cc = fmaf(fg, sm->cstage[j * 65 + e], ig * gv);
                sm->cstage[j * 65 + e] = cc;
                float hn = og * ftanh_(cc);
                sm->hstage[j * 65 + e] = (t == 3) ? fmaxf(hn, 0.0f) : hn;
            }
            __syncwarp();
#pragma unroll
            for (int k = 0; k < 64; ++k) h[k] = sm->hstage[k * 65 + e];
            __syncwarp();
        }
        // h now holds last = relu(h3)

        // ---- comb = relu(Wc @ [r, last] + bc) ----
        {
            int rt = (bp < 4) ? 4 * bp : 0;
            load32(xt, emb + (size_t)xr[rt] * 32);
        }
        for (int mm = 0; mm < 8; ++mm) {
            int m = (q << 3) + mm;
            float acc = sm->bc[m];
#pragma unroll
            for (int k = 0; k < 32; ++k) acc = fmaf(sm->Wc[m * 96 + k], xt[k], acc);
#pragma unroll
            for (int k = 0; k < 64; ++k) acc = fmaf(sm->Wc[m * 96 + 32 + k], h[k], acc);
            float cv = fmaxf(acc, 0.0f);
            if (bp < 4) sm->hid[(bp * 32 + m) * 64 + e] = cv;
            else        sm->hstage[m * 65 + e] = cv;
        }
        __syncwarp();
    }

    // ---- logits + log_softmax (64 tags, split 16 per thread) ----
    float cb[32];
#pragma unroll
    for (int k = 0; k < 32; ++k) cb[k] = sm->hstage[k * 65 + e];
    float lg[16];
    float mx = -1e30f;
#pragma unroll
    for (int mm = 0; mm < 16; ++mm) {
        int m = (q << 4) + mm;
        float acc = sm->bt[m];
#pragma unroll
        for (int k = 0; k < 32; ++k) acc = fmaf(sm->Wt[m * 32 + k], cb[k], acc);
        lg[mm] = acc;
        mx = fmaxf(mx, acc);
    }
    mx = fmaxf(mx, __shfl_xor_sync(0xffffffffu, mx, 1));
    mx = fmaxf(mx, __shfl_xor_sync(0xffffffffu, mx, 2));
    float se = 0.0f;
#pragma unroll
    for (int mm = 0; mm < 16; ++mm) se += __expf(lg[mm] - mx);
    se += __shfl_xor_sync(0xffffffffu, se, 1);
    se += __shfl_xor_sync(0xffffffffu, se, 2);
    float lse = mx + logf(se);
    if (act) {
        float4* o4 = reinterpret_cast<float4*>(out + (size_t)i * 64 + q * 16);
#pragma unroll
        for (int c = 0; c < 4; ++c) {
            float4 v;
            v.x = lg[4 * c + 0] - lse; v.y = lg[4 * c + 1] - lse;
            v.z = lg[4 * c + 2] - lse; v.w = lg[4 * c + 3] - lse;
            o4[c] = v;
        }
    }
}

// ---------------------------------------------------------------------------
extern "C" void kernel_launch(void* const* d_in, const int* in_sizes, int n_in,
                              void* d_out, int out_size)
{
    const int*   x   = (const int*)d_in[0];
    const int*   s   = (const int*)d_in[1];
    const float* emb = (const float*)d_in[2];
    const float* Wih = (const float*)d_in[3];
    const float* Whh = (const float*)d_in[4];
    const float* bih = (const float*)d_in[5];
    const float* bhh = (const float*)d_in[6];
    const float* h0  = (const float*)d_in[7];
    const float* c0  = (const float*)d_in[8];
    const float* Wc  = (const float*)d_in[9];
    const float* bc  = (const float*)d_in[10];
    const float* Wt  = (const float*)d_in[11];
    const float* bt  = (const float*)d_in[12];
    float* out = (float*)d_out;

    int B = in_sizes[1];  // s has B elements
    if (B > MAXB) B = MAXB;

    cudaFuncSetAttribute(k_lstm, cudaFuncAttributeMaxDynamicSharedMemorySize,
                         (int)sizeof(SmemB));

    k_zero<<<1, 1>>>();
    k_trivial<<<(B + 255) / 256, 256>>>(x, s, emb, Wc, bc, Wt, bt, out, B);
    int nblk = (B * 4 + 255) / 256;  // worst case: every element active
    k_lstm<<<nblk, 256, sizeof(SmemB)>>>(x, emb, Wih, Whh, bih, bhh,
                                         h0, c0, Wc, bc, Wt, bt, out);
}

// round 2
// speedup vs baseline: 5.6870x; 5.6870x over previous
#include <cuda_runtime.h>
#include <cstdint>

// ---------------------------------------------------------------------------
// TrivialTreeTagger: B=32768, 5 tree-LSTM blocks (H=64,E=32).
// last = relu(h3)*(s==4): only s==4 elements (~25%) need LSTM work.
// R2: warp-uniform q (broadcast weight LDS, no bank conflicts) + fma.rn.f32x2
// paired over K (2 FMA per fma-pipe issue).
// ---------------------------------------------------------------------------

#define MAXB 32768

__device__ int g_count;
__device__ int g_idx[MAXB];

typedef unsigned long long u64;

__device__ __forceinline__ float fsig(float x) {
    return __fdividef(1.0f, 1.0f + __expf(-x));
}
__device__ __forceinline__ float ftanh_(float x) {
    return __fdividef(2.0f, 1.0f + __expf(-2.0f * x)) - 1.0f;
}
__device__ __forceinline__ void ffma2(u64& a, u64 b, u64 c) {
    asm("fma.rn.f32x2 %0, %1, %2, %0;" : "+l"(a) : "l"(b), "l"(c));
}
__device__ __forceinline__ u64 packf2(float lo, float hi) {
    u64 r; asm("mov.b64 %0, {%1, %2};" : "=l"(r) : "f"(lo), "f"(hi)); return r;
}
__device__ __forceinline__ float hsum2(u64 v) {
    float lo, hi; asm("mov.b64 {%0, %1}, %2;" : "=f"(lo), "=f"(hi) : "l"(v));
    return lo + hi;
}
__device__ __forceinline__ void loadx2(u64 (&x2)[16], const float* __restrict__ src) {
    const ulonglong2* p = reinterpret_cast<const ulonglong2*>(src);
#pragma unroll
    for (int c = 0; c < 8; ++c) { ulonglong2 v = p[c]; x2[2*c] = v.x; x2[2*c+1] = v.y; }
}
__device__ __forceinline__ void load32(float (&dst)[32], const float* __restrict__ src) {
    const float4* p = reinterpret_cast<const float4*>(src);
#pragma unroll
    for (int c = 0; c < 8; ++c) {
        float4 v = p[c];
        dst[4*c] = v.x; dst[4*c+1] = v.y; dst[4*c+2] = v.z; dst[4*c+3] = v.w;
    }
}

// -------------------- kernel 0: reset compaction counter --------------------
__global__ void k_zero() { g_count = 0; }

// -------------------- kernel 1: trivial path + compaction -------------------
__global__ void __launch_bounds__(256) k_trivial(
    const int* __restrict__ x, const int* __restrict__ s,
    const float* __restrict__ emb,
    const float* __restrict__ Wc, const float* __restrict__ bcv,
    const float* __restrict__ Wt, const float* __restrict__ btv,
    float* __restrict__ out, int B)
{
    int i = blockIdx.x * 256 + threadIdx.x;
    bool valid = i < B;
    bool act = valid && (s[i] == 4);
    unsigned bal = __ballot_sync(0xffffffffu, act);
    if (act) {
        int lane = threadIdx.x & 31;
        int leader = __ffs(bal) - 1;
        int pos = 0;
        if (lane == leader) pos = atomicAdd(&g_count, __popc(bal));
        pos = __shfl_sync(bal, pos, leader);
        pos += __popc(bal & ((1u << lane) - 1));
        g_idx[pos] = i;
    } else if (valid) {
        float r[32];
        load32(r, emb + (size_t)x[i * 16] * 32);
        float cb[32];
#pragma unroll
        for (int m = 0; m < 32; ++m) {
            float acc = bcv[m];
            const float4* w = reinterpret_cast<const float4*>(Wc + m * 96);
#pragma unroll
            for (int k = 0; k < 8; ++k) {
                float4 wv = w[k];
                acc = fmaf(wv.x, r[4*k], acc);   acc = fmaf(wv.y, r[4*k+1], acc);
                acc = fmaf(wv.z, r[4*k+2], acc); acc = fmaf(wv.w, r[4*k+3], acc);
            }
            cb[m] = fmaxf(acc, 0.0f);
        }
        float lg[64], mx = -1e30f;
#pragma unroll
        for (int m = 0; m < 64; ++m) {
            float acc = btv[m];
            const float4* w = reinterpret_cast<const float4*>(Wt + m * 32);
#pragma unroll
            for (int k = 0; k < 8; ++k) {
                float4 wv = w[k];
                acc = fmaf(wv.x, cb[4*k], acc);   acc = fmaf(wv.y, cb[4*k+1], acc);
                acc = fmaf(wv.z, cb[4*k+2], acc); acc = fmaf(wv.w, cb[4*k+3], acc);
            }
            lg[m] = acc; mx = fmaxf(mx, acc);
        }
        float se = 0.0f;
#pragma unroll
        for (int m = 0; m < 64; ++m) se += __expf(lg[m] - mx);
        float lse = mx + logf(se);
        float4* o4 = reinterpret_cast<float4*>(out + (size_t)i * 64);
#pragma unroll
        for (int c = 0; c < 16; ++c) {
            float4 v;
            v.x = lg[4*c]-lse; v.y = lg[4*c+1]-lse; v.z = lg[4*c+2]-lse; v.w = lg[4*c+3]-lse;
            o4[c] = v;
        }
    }
}

// -------------------- kernel 2: active-element LSTM pipeline ----------------
// 64 elements/block, 256 thr: e = tid&63, q = tid>>6 (warp-uniform q).
// Weights pre-packed as f32x2 K-pairs in shared, broadcast LDS.
struct SmemB {
    u64  W2[64 * 48 * 4];  // [(j*48+kk)*4 + gate]: (w[2kk], w[2kk+1]) per gate row
    u64  Wc2[32 * 48];     // comb weights K-pairs
    u64  Wt2[64 * 16];     // tag weights K-pairs
    float b4[256];         // [j*4+g] bih+bhh
    float a04[256];        // [j*4+g] b + Whh@h0 (step-0 constant)
    float c0s[64];
    float bc[32];
    float bt[64];
    float hst[64 * 66];    // [e][k] stride 66 (even: 8B-aligned pair reads)
    float cst[64 * 65];    // [e][j] stride 65 (conflict-free scalar rw); scratch later
    float hid[64 * 130];   // [e][c] c<128, stride 130
};

__global__ void __launch_bounds__(256, 1) k_lstm(
    const int* __restrict__ x, const float* __restrict__ emb,
    const float* __restrict__ Wih, const float* __restrict__ Whh,
    const float* __restrict__ bih, const float* __restrict__ bhh,
    const float* __restrict__ h0, const float* __restrict__ c0,
    const float* __restrict__ Wc, const float* __restrict__ bcv,
    const float* __restrict__ Wt, const float* __restrict__ btv,
    float* __restrict__ out)
{
    int cnt = g_count;
    if (blockIdx.x * 64 >= cnt) return;

    extern __shared__ char smraw[];
    SmemB* sm = reinterpret_cast<SmemB*>(smraw);
    int tid = threadIdx.x;

    // ---- shared init ----
    for (int idx = tid; idx < 64 * 48; idx += 256) {
        int j = idx / 48, kk = idx % 48;
#pragma unroll
        for (int gg = 0; gg < 4; ++gg) {
            int row = gg * 64 + j;
            float w0, w1;
            if (kk < 16) { w0 = Wih[row*32 + 2*kk]; w1 = Wih[row*32 + 2*kk + 1]; }
            else { int kh = 2*kk - 32; w0 = Whh[row*64 + kh]; w1 = Whh[row*64 + kh + 1]; }
            sm->W2[idx * 4 + gg] = packf2(w0, w1);
        }
    }
    if (tid < 64) {
        int j = tid;
#pragma unroll
        for (int gg = 0; gg < 4; ++gg) {
            int row = gg * 64 + j;
            float bb = bih[row] + bhh[row];
            sm->b4[j*4 + gg] = bb;
            float aa = bb;
            for (int k = 0; k < 64; ++k) aa = fmaf(Whh[row*64 + k], h0[k], aa);
            sm->a04[j*4 + gg] = aa;
        }
        sm->c0s[j] = c0[j];
        sm->bt[j] = btv[j];
    }
    for (int idx = tid; idx < 32 * 48; idx += 256) {
        int m = idx / 48, kk = idx % 48;
        sm->Wc2[idx] = packf2(Wc[m*96 + 2*kk], Wc[m*96 + 2*kk + 1]);
    }
    for (int idx = tid; idx < 64 * 16; idx += 256) {
        int m = idx / 16, kk = idx % 16;
        sm->Wt2[idx] = packf2(Wt[m*32 + 2*kk], Wt[m*32 + 2*kk + 1]);
    }
    if (tid < 32) sm->bc[tid] = bcv[tid];
    __syncthreads();

    int e = tid & 63;
    int q = tid >> 6;
    int g = blockIdx.x * 64 + e;
    bool act = g < cnt;
    int i = g_idx[act ? g : (cnt - 1)];
    const int* xr = x + i * 16;

    u64 h2[32], xt2[16];
    float* crow = sm->cst + e * 65;
    float* hrow = sm->hst + e * 66;

#pragma unroll 1
    for (int bp = 0; bp < 5; ++bp) {
#pragma unroll 1
        for (int t = 0; t < 4; ++t) {
            if (bp < 4) {
                loadx2(xt2, emb + (size_t)xr[4*bp + t] * 32);
            } else {
#pragma unroll
                for (int kk = 0; kk < 16; ++kk)
                    xt2[kk] = *reinterpret_cast<const u64*>(sm->hid + 130*e + t*32 + 2*kk);
            }
#pragma unroll 1
            for (int jj = 0; jj < 16; ++jj) {
                int j = (q << 4) + jj;
                const ulonglong2* wp = reinterpret_cast<const ulonglong2*>(sm->W2 + j * 192);
                const float* pre = (t == 0) ? (sm->a04 + j*4) : (sm->b4 + j*4);
                u64 a0 = packf2(pre[0], 0.f), a1 = packf2(pre[1], 0.f);
                u64 a2 = packf2(pre[2], 0.f), a3 = packf2(pre[3], 0.f);
#pragma unroll
                for (int kk = 0; kk < 16; ++kk) {
                    ulonglong2 wa = wp[kk*2], wb = wp[kk*2 + 1];
                    u64 xv = xt2[kk];
                    ffma2(a0, wa.x, xv); ffma2(a1, wa.y, xv);
                    ffma2(a2, wb.x, xv); ffma2(a3, wb.y, xv);
                }
                if (t > 0) {
#pragma unroll
                    for (int kk = 0; kk < 32; ++kk) {
                        ulonglong2 wa = wp[32 + kk*2], wb = wp[33 + kk*2];
                        u64 hv = h2[kk];
                        ffma2(a0, wa.x, hv); ffma2(a1, wa.y, hv);
                        ffma2(a2, wb.x, hv); ffma2(a3, wb.y, hv);
                    }
                }
                float iv = fsig(hsum2(a0));
                float fv = fsig(hsum2(a1));
                float gv = ftanh_(hsum2(a2));
                float ov = fsig(hsum2(a3));
                float cprev = (t == 0) ? sm->c0s[j] : crow[j];
                float cc = fmaf(fv, cprev, iv * gv);
                crow[j] = cc;
                float hn = ov * ftanh_(cc);
                hrow[j] = (t == 3) ? fmaxf(hn, 0.f) : hn;
            }
            __syncthreads();
#pragma unroll
            for (int kk = 0; kk < 32; ++kk)
                h2[kk] = *reinterpret_cast<const u64*>(sm->hst + 66*e + 2*kk);
            __syncthreads();
        }

        // ---- comb = relu(Wc @ [r, last] + bc) ----
        {
            int rt = (bp < 4) ? 4*bp : 0;
            loadx2(xt2, emb + (size_t)xr[rt] * 32);
        }
#pragma unroll 1
        for (int mm = 0; mm < 8; ++mm) {
            int m = (q << 3) + mm;
            const u64* wp = sm->Wc2 + m * 48;
            u64 acc = packf2(sm->bc[m], 0.f);
#pragma unroll
            for (int kk = 0; kk < 16; ++kk) ffma2(acc, wp[kk], xt2[kk]);
#pragma unroll
            for (int kk = 0; kk < 32; ++kk) ffma2(acc, wp[16 + kk], h2[kk]);
            float cv = fmaxf(hsum2(acc), 0.f);
            if (bp < 4) sm->hid[130*e + bp*32 + m] = cv;
            else        sm->hst[66*e + m] = cv;
        }
        __syncthreads();
    }

    // ---- logits + log_softmax ----
    u64 cb2[16];
#pragma unroll
    for (int kk = 0; kk < 16; ++kk)
        cb2[kk] = *reinterpret_cast<const u64*>(sm->hst + 66*e + 2*kk);
    float lg[16], mx = -1e30f;
#pragma unroll
    for (int mm = 0; mm < 16; ++mm) {
        int m = (q << 4) + mm;
        const u64* wp = sm->Wt2 + m * 16;
        u64 acc = packf2(sm->bt[m], 0.f);
#pragma unroll
        for (int kk = 0; kk < 16; ++kk) ffma2(acc, wp[kk], cb2[kk]);
        lg[mm] = hsum2(acc);
        mx = fmaxf(mx, lg[mm]);
    }
    // cross-warp (4 q slices) reduction via cst scratch
    sm->cst[q * 64 + e] = mx;
    __syncthreads();
    float fmx = fmaxf(fmaxf(sm->cst[e], sm->cst[64 + e]),
                      fmaxf(sm->cst[128 + e], sm->cst[192 + e]));
    float se = 0.f;
#pragma unroll
    for (int mm = 0; mm < 16; ++mm) se += __expf(lg[mm] - fmx);
    sm->cst[256 + q * 64 + e] = se;
    __syncthreads();
    float tse = sm->cst[256 + e] + sm->cst[320 + e] + sm->cst[384 + e] + sm->cst[448 + e];
    float lse = fmx + logf(tse);
    if (act) {
        float4* o4 = reinterpret_cast<float4*>(out + (size_t)i * 64 + q * 16);
#pragma unroll
        for (int c = 0; c < 4; ++c) {
            float4 v;
            v.x = lg[4*c]-lse; v.y = lg[4*c+1]-lse; v.z = lg[4*c+2]-lse; v.w = lg[4*c+3]-lse;
            o4[c] = v;
        }
    }
}

// ---------------------------------------------------------------------------
extern "C" void kernel_launch(void* const* d_in, const int* in_sizes, int n_in,
                              void* d_out, int out_size)
{
    const int*   x   = (const int*)d_in[0];
    const int*   s   = (const int*)d_in[1];
    const float* emb = (const float*)d_in[2];
    const float* Wih = (const float*)d_in[3];
    const float* Whh = (const float*)d_in[4];
    const float* bih = (const float*)d_in[5];
    const float* bhh = (const float*)d_in[6];
    const float* h0  = (const float*)d_in[7];
    const float* c0  = (const float*)d_in[8];
    const float* Wc  = (const float*)d_in[9];
    const float* bc  = (const float*)d_in[10];
    const float* Wt  = (const float*)d_in[11];
    const float* bt  = (const float*)d_in[12];
    float* out = (float*)d_out;

    int B = in_sizes[1];
    if (B > MAXB) B = MAXB;

    cudaFuncSetAttribute(k_lstm, cudaFuncAttributeMaxDynamicSharedMemorySize,
                         (int)sizeof(SmemB));

    k_zero<<<1, 1>>>();
    k_trivial<<<(B + 255) / 256, 256>>>(x, s, emb, Wc, bc, Wt, bt, out, B);
    int nblk = (B + 63) / 64;  // worst case: every element active
    k_lstm<<<nblk, 256, sizeof(SmemB)>>>(x, emb, Wih, Whh, bih, bhh,
                                         h0, c0, Wc, bc, Wt, bt, out);
}

// round 3
// speedup vs baseline: 6.1096x; 1.0743x over previous
#include <cuda_runtime.h>
#include <cstdint>

// ---------------------------------------------------------------------------
// TrivialTreeTagger: B=32768, 5 tree-LSTM blocks (H=64,E=32).
// last = relu(h3)*(s==4): only s==4 elements (~25%) need LSTM work.
// R3: MUFU.TANH nonlinearities, unroll-2 row loop, emb prefetch,
// double-buffered h (1 sync/step), conflict-free [k][e] staging,
// trivial path fused into idle blocks of the main kernel.
// ---------------------------------------------------------------------------

#define MAXB 32768

struct Counters { int act; int triv; };
__device__ Counters g_cnt;
__device__ int g_idx[MAXB];
__device__ int g_tidx[MAXB];

typedef unsigned long long u64;

__device__ __forceinline__ float ftanh_(float x) {
    float r; asm("tanh.approx.f32 %0, %1;" : "=f"(r) : "f"(x)); return r;
}
__device__ __forceinline__ float fsig(float x) {
    return fmaf(0.5f, ftanh_(0.5f * x), 0.5f);
}
__device__ __forceinline__ void ffma2(u64& a, u64 b, u64 c) {
    asm("fma.rn.f32x2 %0, %1, %2, %0;" : "+l"(a) : "l"(b), "l"(c));
}
__device__ __forceinline__ u64 packf2(float lo, float hi) {
    u64 r; asm("mov.b64 %0, {%1, %2};" : "=l"(r) : "f"(lo), "f"(hi)); return r;
}
__device__ __forceinline__ float hsum2(u64 v) {
    float lo, hi; asm("mov.b64 {%0, %1}, %2;" : "=f"(lo), "=f"(hi) : "l"(v));
    return lo + hi;
}
__device__ __forceinline__ void loadx2(u64 (&x2)[16], const float* __restrict__ src) {
    const ulonglong2* p = reinterpret_cast<const ulonglong2*>(src);
#pragma unroll
    for (int c = 0; c < 8; ++c) { ulonglong2 v = p[c]; x2[2*c] = v.x; x2[2*c+1] = v.y; }
}
__device__ __forceinline__ void load32(float (&dst)[32], const float* __restrict__ src) {
    const float4* p = reinterpret_cast<const float4*>(src);
#pragma unroll
    for (int c = 0; c < 8; ++c) {
        float4 v = p[c];
        dst[4*c] = v.x; dst[4*c+1] = v.y; dst[4*c+2] = v.z; dst[4*c+3] = v.w;
    }
}

// -------------------- kernel 1: compaction only ------------------------------
__global__ void __launch_bounds__(256) k_compact(const int* __restrict__ s, int B)
{
    int i = blockIdx.x * 256 + threadIdx.x;
    bool valid = i < B;
    bool a = valid && (s[i] == 4);
    bool t = valid && !a;
    unsigned ba = __ballot_sync(0xffffffffu, a);
    unsigned bt = __ballot_sync(0xffffffffu, t);
    int lane = threadIdx.x & 31;
    if (a) {
        int leader = __ffs(ba) - 1;
        int pos = 0;
        if (lane == leader) pos = atomicAdd(&g_cnt.act, __popc(ba));
        pos = __shfl_sync(ba, pos, leader);
        g_idx[pos + __popc(ba & ((1u << lane) - 1))] = i;
    } else if (t) {
        int leader = __ffs(bt) - 1;
        int pos = 0;
        if (lane == leader) pos = atomicAdd(&g_cnt.triv, __popc(bt));
        pos = __shfl_sync(bt, pos, leader);
        g_tidx[pos + __popc(bt & ((1u << lane) - 1))] = i;
    }
}

// -------------------- kernel 2: fused main -----------------------------------
struct SmemB {
    u64  W2[64 * 48 * 4];   // [(j*48+kk)*4 + gate]: (w[2kk], w[2kk+1]) per gate row
    u64  Wc2[32 * 48];      // comb weights K-pairs
    u64  Wt2[64 * 16];      // tag weights K-pairs
    float4 b44[64];         // gate biases per j (i,f,g,o)
    float4 a044[64];        // bias + Whh@h0 (step-0 constant)
    float c0s[64];
    float bc[32];
    float bt[64];
    float hbuf[2][64 * 65]; // [buf][k*65 + e] (conflict-free scalar access)
    float cstg[64 * 65];    // [e*65 + j] cell state (conflict-free)
    float hidc[128 * 65];   // [c*65 + e] hidden[0..3] combs
    float cbf[32 * 65];     // [m*65 + e] final comb
    float red[8 * 64];      // epilogue reductions
};

__global__ void __launch_bounds__(256, 1) k_main(
    const int* __restrict__ x, const float* __restrict__ emb,
    const float* __restrict__ Wih, const float* __restrict__ Whh,
    const float* __restrict__ bih, const float* __restrict__ bhh,
    const float* __restrict__ h0, const float* __restrict__ c0,
    const float* __restrict__ Wc, const float* __restrict__ bcv,
    const float* __restrict__ Wt, const float* __restrict__ btv,
    float* __restrict__ out, int B)
{
    int cnt = g_cnt.act;
    int nl = (cnt + 63) >> 6;   // number of LSTM blocks
    int tid = threadIdx.x;

    if ((int)blockIdx.x >= nl) {
        // -------------------- trivial path (idle blocks) --------------------
        int tcnt = g_cnt.triv;
        int ntriv = gridDim.x - nl;
        for (int c = blockIdx.x - nl; c * 256 < tcnt; c += ntriv) {
            int ti = c * 256 + tid;
            if (ti >= tcnt) continue;
            int i = g_tidx[ti];
            float r[32];
            load32(r, emb + (size_t)x[i * 16] * 32);
            float cb[32];
#pragma unroll
            for (int m = 0; m < 32; ++m) {
                float acc = bcv[m];
                const float4* w = reinterpret_cast<const float4*>(Wc + m * 96);
#pragma unroll
                for (int k = 0; k < 8; ++k) {
                    float4 wv = w[k];
                    acc = fmaf(wv.x, r[4*k], acc);   acc = fmaf(wv.y, r[4*k+1], acc);
                    acc = fmaf(wv.z, r[4*k+2], acc); acc = fmaf(wv.w, r[4*k+3], acc);
                }
                cb[m] = fmaxf(acc, 0.0f);
            }
            float lg[64], mx = -1e30f;
#pragma unroll
            for (int m = 0; m < 64; ++m) {
                float acc = btv[m];
                const float4* w = reinterpret_cast<const float4*>(Wt + m * 32);
#pragma unroll
                for (int k = 0; k < 8; ++k) {
                    float4 wv = w[k];
                    acc = fmaf(wv.x, cb[4*k], acc);   acc = fmaf(wv.y, cb[4*k+1], acc);
                    acc = fmaf(wv.z, cb[4*k+2], acc); acc = fmaf(wv.w, cb[4*k+3], acc);
                }
                lg[m] = acc; mx = fmaxf(mx, acc);
            }
            float se = 0.0f;
#pragma unroll
            for (int m = 0; m < 64; ++m) se += __expf(lg[m] - mx);
            float lse = mx + logf(se);
            float4* o4 = reinterpret_cast<float4*>(out + (size_t)i * 64);
#pragma unroll
            for (int cc = 0; cc < 16; ++cc) {
                float4 v;
                v.x = lg[4*cc]-lse; v.y = lg[4*cc+1]-lse;
                v.z = lg[4*cc+2]-lse; v.w = lg[4*cc+3]-lse;
                o4[cc] = v;
            }
        }
        return;
    }

    // ------------------------- LSTM path ------------------------------------
    extern __shared__ char smraw[];
    SmemB* sm = reinterpret_cast<SmemB*>(smraw);

    // ---- shared init ----
    for (int idx = tid; idx < 64 * 48; idx += 256) {
        int j = idx / 48, kk = idx % 48;
#pragma unroll
        for (int gg = 0; gg < 4; ++gg) {
            int row = gg * 64 + j;
            float w0, w1;
            if (kk < 16) { w0 = Wih[row*32 + 2*kk]; w1 = Wih[row*32 + 2*kk + 1]; }
            else { int kh = 2*kk - 32; w0 = Whh[row*64 + kh]; w1 = Whh[row*64 + kh + 1]; }
            sm->W2[idx * 4 + gg] = packf2(w0, w1);
        }
    }
    if (tid < 64) {
        int j = tid;
        float4 bb, aa;
        float* bp_ = reinterpret_cast<float*>(&bb);
        float* ap_ = reinterpret_cast<float*>(&aa);
#pragma unroll
        for (int gg = 0; gg < 4; ++gg) {
            int row = gg * 64 + j;
            float b = bih[row] + bhh[row];
            bp_[gg] = b;
            float a = b;
            for (int k = 0; k < 64; ++k) a = fmaf(Whh[row*64 + k], h0[k], a);
            ap_[gg] = a;
        }
        sm->b44[j] = bb;
        sm->a044[j] = aa;
        sm->c0s[j] = c0[j];
        sm->bt[j] = btv[j];
    }
    for (int idx = tid; idx < 32 * 48; idx += 256) {
        int m = idx / 48, kk = idx % 48;
        sm->Wc2[idx] = packf2(Wc[m*96 + 2*kk], Wc[m*96 + 2*kk + 1]);
    }
    for (int idx = tid; idx < 64 * 16; idx += 256) {
        int m = idx / 16, kk = idx % 16;
        sm->Wt2[idx] = packf2(Wt[m*32 + 2*kk], Wt[m*32 + 2*kk + 1]);
    }
    if (tid < 32) sm->bc[tid] = bcv[tid];
    __syncthreads();

    int e = tid & 63;
    int q = tid >> 6;
    int g = blockIdx.x * 64 + e;
    bool act = g < cnt;
    int i = g_idx[act ? g : (cnt - 1)];
    const int* xr = x + i * 16;

    u64 xt2[16], xn2[16], h2[32];
    float* crow = sm->cstg + e * 65;

    loadx2(xt2, emb + (size_t)xr[0] * 32);
    int step = 0;

#pragma unroll 1
    for (int bp = 0; bp < 5; ++bp) {
#pragma unroll 1
        for (int t = 0; t < 4; ++t) {
            if (bp == 4) {
#pragma unroll
                for (int kk = 0; kk < 16; ++kk)
                    xt2[kk] = packf2(sm->hidc[(t*32 + 2*kk)*65 + e],
                                     sm->hidc[(t*32 + 2*kk + 1)*65 + e]);
            }
            int nxt = 4*bp + t + 1;
            bool pf = (bp < 4) && (nxt < 16);
            if (pf) loadx2(xn2, emb + (size_t)xr[nxt] * 32);   // prefetch

            const float4* preb = (t == 0) ? sm->a044 : sm->b44;
            float* hw = sm->hbuf[step & 1];
#pragma unroll 2
            for (int jj = 0; jj < 16; ++jj) {
                int j = (q << 4) + jj;
                const ulonglong2* wp = reinterpret_cast<const ulonglong2*>(sm->W2 + j * 192);
                float4 pv = preb[j];
                u64 a0 = packf2(pv.x, 0.f), a1 = packf2(pv.y, 0.f);
                u64 a2 = packf2(pv.z, 0.f), a3 = packf2(pv.w, 0.f);
#pragma unroll
                for (int kk = 0; kk < 16; ++kk) {
                    ulonglong2 wa = wp[kk*2], wb = wp[kk*2 + 1];
                    u64 xv = xt2[kk];
                    ffma2(a0, wa.x, xv); ffma2(a1, wa.y, xv);
                    ffma2(a2, wb.x, xv); ffma2(a3, wb.y, xv);
                }
                if (t > 0) {
#pragma unroll
                    for (int kk = 0; kk < 32; ++kk) {
                        ulonglong2 wa = wp[32 + kk*2], wb = wp[33 + kk*2];
                        u64 hv = h2[kk];
                        ffma2(a0, wa.x, hv); ffma2(a1, wa.y, hv);
                        ffma2(a2, wb.x, hv); ffma2(a3, wb.y, hv);
                    }
                }
                float iv = fsig(hsum2(a0));
                float fv = fsig(hsum2(a1));
                float gv = ftanh_(hsum2(a2));
                float ov = fsig(hsum2(a3));
                float cprev = (t == 0) ? sm->c0s[j] : crow[j];
                float cc = fmaf(fv, cprev, iv * gv);
                crow[j] = cc;
                float hn = ov * ftanh_(cc);
                hw[j * 65 + e] = (t == 3) ? fmaxf(hn, 0.f) : hn;
            }
            __syncthreads();
#pragma unroll
            for (int kk = 0; kk < 32; ++kk)
                h2[kk] = packf2(hw[(2*kk)*65 + e], hw[(2*kk + 1)*65 + e]);
            if (pf) {
#pragma unroll
                for (int kk = 0; kk < 16; ++kk) xt2[kk] = xn2[kk];
            }
            step++;
        }

        // ---- comb = relu(Wc @ [r, last] + bc); r = emb[root token] ----
        loadx2(xn2, emb + (size_t)xr[(bp < 4) ? 4*bp : 0] * 32);
#pragma unroll 2
        for (int mm = 0; mm < 8; ++mm) {
            int m = (q << 3) + mm;
            const u64* wp = sm->Wc2 + m * 48;
            u64 acc = packf2(sm->bc[m], 0.f);
#pragma unroll
            for (int kk = 0; kk < 16; ++kk) ffma2(acc, wp[kk], xn2[kk]);
#pragma unroll
            for (int kk = 0; kk < 32; ++kk) ffma2(acc, wp[16 + kk], h2[kk]);
            float cv = fmaxf(hsum2(acc), 0.f);
            if (bp < 4) sm->hidc[(bp*32 + m)*65 + e] = cv;
            else        sm->cbf[m*65 + e] = cv;
        }
        __syncthreads();
    }

    // ---- logits + log_softmax ----
    u64 cb2[16];
#pragma unroll
    for (int kk = 0; kk < 16; ++kk)
        cb2[kk] = packf2(sm->cbf[(2*kk)*65 + e], sm->cbf[(2*kk + 1)*65 + e]);
    float lg[16], mx = -1e30f;
#pragma unroll
    for (int mm = 0; mm < 16; ++mm) {
        int m = (q << 4) + mm;
        const u64* wp = sm->Wt2 + m * 16;
        u64 acc = packf2(sm->bt[m], 0.f);
#pragma unroll
        for (int kk = 0; kk < 16; ++kk) ffma2(acc, wp[kk], cb2[kk]);
        lg[mm] = hsum2(acc);
        mx = fmaxf(mx, lg[mm]);
    }
    sm->red[q * 64 + e] = mx;
    __syncthreads();
    float fmx = fmaxf(fmaxf(sm->red[e], sm->red[64 + e]),
                      fmaxf(sm->red[128 + e], sm->red[192 + e]));
    float se = 0.f;
#pragma unroll
    for (int mm = 0; mm < 16; ++mm) se += __expf(lg[mm] - fmx);
    sm->red[256 + q * 64 + e] = se;
    __syncthreads();
    float tse = sm->red[256 + e] + sm->red[320 + e] + sm->red[384 + e] + sm->red[448 + e];
    float lse = fmx + logf(tse);
    if (act) {
        float4* o4 = reinterpret_cast<float4*>(out + (size_t)i * 64 + q * 16);
#pragma unroll
        for (int c = 0; c < 4; ++c) {
            float4 v;
            v.x = lg[4*c]-lse; v.y = lg[4*c+1]-lse; v.z = lg[4*c+2]-lse; v.w = lg[4*c+3]-lse;
            o4[c] = v;
        }
    }
}

// ---------------------------------------------------------------------------
extern "C" void kernel_launch(void* const* d_in, const int* in_sizes, int n_in,
                              void* d_out, int out_size)
{
    const int*   x   = (const int*)d_in[0];
    const int*   s   = (const int*)d_in[1];
    const float* emb = (const float*)d_in[2];
    const float* Wih = (const float*)d_in[3];
    const float* Whh = (const float*)d_in[4];
    const float* bih = (const float*)d_in[5];
    const float* bhh = (const float*)d_in[6];
    const float* h0  = (const float*)d_in[7];
    const float* c0  = (const float*)d_in[8];
    const float* Wc  = (const float*)d_in[9];
    const float* bc  = (const float*)d_in[10];
    const float* Wt  = (const float*)d_in[11];
    const float* bt  = (const float*)d_in[12];
    float* out = (float*)d_out;

    int B = in_sizes[1];
    if (B > MAXB) B = MAXB;

    cudaFuncSetAttribute(k_main, cudaFuncAttributeMaxDynamicSharedMemorySize,
                         (int)sizeof(SmemB));

    void* cptr = nullptr;
    cudaGetSymbolAddress(&cptr, g_cnt);
    cudaMemsetAsync(cptr, 0, sizeof(Counters));

    k_compact<<<(B + 255) / 256, 256>>>(s, B);
    int nblk = (B + 63) / 64;
    k_main<<<nblk, 256, sizeof(SmemB)>>>(x, emb, Wih, Whh, bih, bhh,
                                         h0, c0, Wc, bc, Wt, bt, out, B);
}

// round 5
// speedup vs baseline: 6.2505x; 1.0231x over previous
#include <cuda_runtime.h>
#include <cstdint>

// ---------------------------------------------------------------------------
// TrivialTreeTagger: B=32768, 5 tree-LSTM blocks (H=64,E=32).
// last = relu(h3)*(s==4): only s==4 elements (~25%) need LSTM work.
// R4: 2 elements per lane (8 rows/warp) -> 1 weight LDS.128 : 4 ffma2,
// flipping the kernel from L1-bound (78.5%) to FMA-bound. Emb prefetch via
// cp.async double buffer (no extra regs). cstg reused as epilogue scratch.
// ---------------------------------------------------------------------------

#define MAXB 32768

struct Counters { int act; int triv; };
__device__ Counters g_cnt;
__device__ int g_idx[MAXB];
__device__ int g_tidx[MAXB];

typedef unsigned long long u64;

__device__ __forceinline__ float ftanh_(float x) {
    float r; asm("tanh.approx.f32 %0, %1;" : "=f"(r) : "f"(x)); return r;
}
__device__ __forceinline__ float fsig(float x) {
    return fmaf(0.5f, ftanh_(0.5f * x), 0.5f);
}
__device__ __forceinline__ void ffma2(u64& a, u64 b, u64 c) {
    asm("fma.rn.f32x2 %0, %1, %2, %0;" : "+l"(a) : "l"(b), "l"(c));
}
__device__ __forceinline__ u64 packf2(float lo, float hi) {
    u64 r; asm("mov.b64 %0, {%1, %2};" : "=l"(r) : "f"(lo), "f"(hi)); return r;
}
__device__ __forceinline__ float hsum2(u64 v) {
    float lo, hi; asm("mov.b64 {%0, %1}, %2;" : "=f"(lo), "=f"(hi) : "l"(v));
    return lo + hi;
}
__device__ __forceinline__ uint32_t smem_u32(const void* p) {
    uint32_t a;
    asm("{ .reg .u64 t; cvta.to.shared.u64 t, %1; cvt.u32.u64 %0, t; }"
        : "=r"(a) : "l"(p));
    return a;
}
__device__ __forceinline__ void cpasync16(uint32_t dst, const void* src) {
    asm volatile("cp.async.ca.shared.global [%0], [%1], 16;" :: "r"(dst), "l"(src));
}
__device__ __forceinline__ void loadx2(u64 (&x2)[16], const void* __restrict__ src) {
    const ulonglong2* p = reinterpret_cast<const ulonglong2*>(src);
#pragma unroll
    for (int c = 0; c < 8; ++c) { ulonglong2 v = p[c]; x2[2*c] = v.x; x2[2*c+1] = v.y; }
}
__device__ __forceinline__ void load32(float (&dst)[32], const float* __restrict__ src) {
    const float4* p = reinterpret_cast<const float4*>(src);
#pragma unroll
    for (int c = 0; c < 8; ++c) {
        float4 v = p[c];
        dst[4*c] = v.x; dst[4*c+1] = v.y; dst[4*c+2] = v.z; dst[4*c+3] = v.w;
    }
}

// -------------------- kernel 1: compaction ----------------------------------
__global__ void __launch_bounds__(256) k_compact(const int* __restrict__ s, int B)
{
    int i = blockIdx.x * 256 + threadIdx.x;
    bool valid = i < B;
    bool a = valid && (s[i] == 4);
    bool t = valid && !a;
    unsigned ba = __ballot_sync(0xffffffffu, a);
    unsigned bt = __ballot_sync(0xffffffffu, t);
    int lane = threadIdx.x & 31;
    if (a) {
        int leader = __ffs(ba) - 1;
        int pos = 0;
        if (lane == leader) pos = atomicAdd(&g_cnt.act, __popc(ba));
        pos = __shfl_sync(ba, pos, leader);
        g_idx[pos + __popc(ba & ((1u << lane) - 1))] = i;
    } else if (t) {
        int leader = __ffs(bt) - 1;
        int pos = 0;
        if (lane == leader) pos = atomicAdd(&g_cnt.triv, __popc(bt));
        pos = __shfl_sync(bt, pos, leader);
        g_tidx[pos + __popc(bt & ((1u << lane) - 1))] = i;
    }
}

// -------------------- kernel 2: fused main ----------------------------------
struct SmemB {
    u64  W2[64 * 48 * 4];      // [(j*48+kk)*4+gate]: K-pair per gate row
    u64  Wc2[32 * 48];
    u64  Wt2[64 * 16];
    float4 b44[64];
    float4 a044[64];
    float c0s[64];
    float bc[32];
    float bt[64];
    float hbuf[2][64 * 65];    // [buf][j*65+e]
    float cstg[64 * 65];       // [e*65+j] cell; later epilogue scratch
    float hidc[128 * 65];      // [row*65+e] combs (bp4 comb overlays rows 0..31)
    float xstage[2][64][32];   // cp.async x double-buffer
};

__global__ void __launch_bounds__(256, 1) k_main(
    const int* __restrict__ x, const float* __restrict__ emb,
    const float* __restrict__ Wih, const float* __restrict__ Whh,
    const float* __restrict__ bih, const float* __restrict__ bhh,
    const float* __restrict__ h0, const float* __restrict__ c0,
    const float* __restrict__ Wc, const float* __restrict__ bcv,
    const float* __restrict__ Wt, const float* __restrict__ btv,
    float* __restrict__ out, int B)
{
    int cnt = g_cnt.act;
    int nl = (cnt + 63) >> 6;
    int tid = threadIdx.x;

    if ((int)blockIdx.x >= nl) {
        // -------------------- trivial path (idle blocks) --------------------
        int tcnt = g_cnt.triv;
        int ntriv = gridDim.x - nl;
        for (int c = blockIdx.x - nl; c * 256 < tcnt; c += ntriv) {
            int ti = c * 256 + tid;
            if (ti >= tcnt) continue;
            int i = g_tidx[ti];
            float r[32];
            load32(r, emb + (size_t)x[i * 16] * 32);
            float cb[32];
#pragma unroll
            for (int m = 0; m < 32; ++m) {
                float acc = bcv[m];
                const float4* w = reinterpret_cast<const float4*>(Wc + m * 96);
#pragma unroll
                for (int k = 0; k < 8; ++k) {
                    float4 wv = w[k];
                    acc = fmaf(wv.x, r[4*k], acc);   acc = fmaf(wv.y, r[4*k+1], acc);
                    acc = fmaf(wv.z, r[4*k+2], acc); acc = fmaf(wv.w, r[4*k+3], acc);
                }
                cb[m] = fmaxf(acc, 0.0f);
            }
            float lg[64], mx = -1e30f;
#pragma unroll
            for (int m = 0; m < 64; ++m) {
                float acc = btv[m];
                const float4* w = reinterpret_cast<const float4*>(Wt + m * 32);
#pragma unroll
                for (int k = 0; k < 8; ++k) {
                    float4 wv = w[k];
                    acc = fmaf(wv.x, cb[4*k], acc);   acc = fmaf(wv.y, cb[4*k+1], acc);
                    acc = fmaf(wv.z, cb[4*k+2], acc); acc = fmaf(wv.w, cb[4*k+3], acc);
                }
                lg[m] = acc; mx = fmaxf(mx, acc);
            }
            float se = 0.0f;
#pragma unroll
            for (int m = 0; m < 64; ++m) se += __expf(lg[m] - mx);
            float lse = mx + logf(se);
            float4* o4 = reinterpret_cast<float4*>(out + (size_t)i * 64);
#pragma unroll
            for (int cc = 0; cc < 16; ++cc) {
                float4 v;
                v.x = lg[4*cc]-lse; v.y = lg[4*cc+1]-lse;
                v.z = lg[4*cc+2]-lse; v.w = lg[4*cc+3]-lse;
                o4[cc] = v;
            }
        }
        return;
    }

    // ------------------------- LSTM path ------------------------------------
    extern __shared__ char smraw[];
    SmemB* sm = reinterpret_cast<SmemB*>(smraw);

    int lane = tid & 31;
    int w = tid >> 5;
    int e0 = lane, e1 = lane + 32;
    int gA = blockIdx.x * 64 + e0, gB = blockIdx.x * 64 + e1;
    bool actA = gA < cnt, actB = gB < cnt;
    int iA = g_idx[gA < cnt ? gA : (cnt - 1)];
    int iB = g_idx[gB < cnt ? gB : (cnt - 1)];
    const int* xrA = x + iA * 16;
    const int* xrB = x + iB * 16;

    // prefetcher identity: thread tid<64 feeds element e=tid
    const int* xrP = nullptr;
    uint32_t xsbase = smem_u32(&sm->xstage[0][0][0]);
    if (tid < 64) {
        int gp = blockIdx.x * 64 + tid;
        xrP = x + (size_t)g_idx[gp < cnt ? gp : (cnt - 1)] * 16;
        // prefetch step 0 into xstage[0]
        const float* src = emb + (size_t)xrP[0] * 32;
        uint32_t dst = xsbase + tid * 128;
#pragma unroll
        for (int c = 0; c < 8; ++c) cpasync16(dst + c * 16, src + c * 4);
        asm volatile("cp.async.commit_group;" ::: "memory");
    }

    // ---- shared init ----
    for (int idx = tid; idx < 64 * 48; idx += 256) {
        int j = idx / 48, kk = idx % 48;
#pragma unroll
        for (int gg = 0; gg < 4; ++gg) {
            int row = gg * 64 + j;
            float w0, w1;
            if (kk < 16) { w0 = Wih[row*32 + 2*kk]; w1 = Wih[row*32 + 2*kk + 1]; }
            else { int kh = 2*kk - 32; w0 = Whh[row*64 + kh]; w1 = Whh[row*64 + kh + 1]; }
            sm->W2[idx * 4 + gg] = packf2(w0, w1);
        }
    }
    if (tid < 64) {
        int j = tid;
        float4 bb, aa;
        float* bp_ = reinterpret_cast<float*>(&bb);
        float* ap_ = reinterpret_cast<float*>(&aa);
#pragma unroll
        for (int gg = 0; gg < 4; ++gg) {
            int row = gg * 64 + j;
            float b = bih[row] + bhh[row];
            bp_[gg] = b;
            float a = b;
            for (int k = 0; k < 64; ++k) a = fmaf(Whh[row*64 + k], h0[k], a);
            ap_[gg] = a;
        }
        sm->b44[j] = bb;
        sm->a044[j] = aa;
        sm->c0s[j] = c0[j];
        sm->bt[j] = btv[j];
    }
    for (int idx = tid; idx < 32 * 48; idx += 256) {
        int m = idx / 48, kk = idx % 48;
        sm->Wc2[idx] = packf2(Wc[m*96 + 2*kk], Wc[m*96 + 2*kk + 1]);
    }
    for (int idx = tid; idx < 64 * 16; idx += 256) {
        int m = idx / 16, kk = idx % 16;
        sm->Wt2[idx] = packf2(Wt[m*32 + 2*kk], Wt[m*32 + 2*kk + 1]);
    }
    if (tid < 32) sm->bc[tid] = bcv[tid];
    asm volatile("cp.async.wait_group 0;" ::: "memory");
    __syncthreads();

    u64 xa[16], xb[16], ha[32], hb[32];
    float* crowA = sm->cstg + e0 * 65;
    float* crowB = sm->cstg + e1 * 65;

    int step = 0;
#pragma unroll 1
    for (int bp = 0; bp < 5; ++bp) {
#pragma unroll 1
        for (int t = 0; t < 4; ++t) {
            int b = step & 1;
            if (bp < 4) {
                loadx2(xa, &sm->xstage[b][e0][0]);
                loadx2(xb, &sm->xstage[b][e1][0]);
            } else {
#pragma unroll
                for (int kk = 0; kk < 16; ++kk) {
                    xa[kk] = packf2(sm->hidc[(t*32 + 2*kk)*65 + e0],
                                    sm->hidc[(t*32 + 2*kk + 1)*65 + e0]);
                    xb[kk] = packf2(sm->hidc[(t*32 + 2*kk)*65 + e1],
                                    sm->hidc[(t*32 + 2*kk + 1)*65 + e1]);
                }
            }
            int nxt = step + 1;
            if (nxt < 16 && tid < 64) {
                const float* src = emb + (size_t)xrP[nxt] * 32;
                uint32_t dst = xsbase + (nxt & 1) * 8192 + tid * 128;
#pragma unroll
                for (int c = 0; c < 8; ++c) cpasync16(dst + c * 16, src + c * 4);
                asm volatile("cp.async.commit_group;" ::: "memory");
            }

            const float4* preb = (t == 0) ? sm->a044 : sm->b44;
            float* hw = sm->hbuf[b];
#pragma unroll 1
            for (int jr = 0; jr < 8; ++jr) {
                int j = (w << 3) + jr;
                const ulonglong2* wp = reinterpret_cast<const ulonglong2*>(sm->W2 + j * 192);
                float4 pv = preb[j];
                u64 a0A = packf2(pv.x, 0.f), a1A = packf2(pv.y, 0.f);
                u64 a2A = packf2(pv.z, 0.f), a3A = packf2(pv.w, 0.f);
                u64 a0B = packf2(pv.x, 0.f), a1B = packf2(pv.y, 0.f);
                u64 a2B = packf2(pv.z, 0.f), a3B = packf2(pv.w, 0.f);
#pragma unroll
                for (int kk = 0; kk < 16; ++kk) {
                    ulonglong2 wa = wp[kk*2], wb = wp[kk*2 + 1];
                    u64 xvA = xa[kk], xvB = xb[kk];
                    ffma2(a0A, wa.x, xvA); ffma2(a1A, wa.y, xvA);
                    ffma2(a2A, wb.x, xvA); ffma2(a3A, wb.y, xvA);
                    ffma2(a0B, wa.x, xvB); ffma2(a1B, wa.y, xvB);
                    ffma2(a2B, wb.x, xvB); ffma2(a3B, wb.y, xvB);
                }
                if (t > 0) {
#pragma unroll
                    for (int kk = 0; kk < 32; ++kk) {
                        ulonglong2 wa = wp[32 + kk*2], wb = wp[33 + kk*2];
                        u64 hvA = ha[kk], hvB = hb[kk];
                        ffma2(a0A, wa.x, hvA); ffma2(a1A, wa.y, hvA);
                        ffma2(a2A, wb.x, hvA); ffma2(a3A, wb.y, hvA);
                        ffma2(a0B, wa.x, hvB); ffma2(a1B, wa.y, hvB);
                        ffma2(a2B, wb.x, hvB); ffma2(a3B, wb.y, hvB);
                    }
                }
                {
                    float iv = fsig(hsum2(a0A)), fv = fsig(hsum2(a1A));
                    float gv = ftanh_(hsum2(a2A)), ov = fsig(hsum2(a3A));
                    float cp = (t == 0) ? sm->c0s[j] : crowA[j];
                    float cc = fmaf(fv, cp, iv * gv);
                    crowA[j] = cc;
                    float hn = ov * ftanh_(cc);
                    hw[j * 65 + e0] = (t == 3) ? fmaxf(hn, 0.f) : hn;
                }
                {
                    float iv = fsig(hsum2(a0B)), fv = fsig(hsum2(a1B));
                    float gv = ftanh_(hsum2(a2B)), ov = fsig(hsum2(a3B));
                    float cp = (t == 0) ? sm->c0s[j] : crowB[j];
                    float cc = fmaf(fv, cp, iv * gv);
                    crowB[j] = cc;
                    float hn = ov * ftanh_(cc);
                    hw[j * 65 + e1] = (t == 3) ? fmaxf(hn, 0.f) : hn;
                }
            }
            asm volatile("cp.async.wait_group 0;" ::: "memory");
            __syncthreads();
#pragma unroll
            for (int kk = 0; kk < 32; ++kk) {
                ha[kk] = packf2(hw[(2*kk)*65 + e0], hw[(2*kk + 1)*65 + e0]);
                hb[kk] = packf2(hw[(2*kk)*65 + e1], hw[(2*kk + 1)*65 + e1]);
            }
            step++;
        }

        // ---- comb = relu(Wc @ [r, last] + bc) ----
        {
            int rt = (bp < 4) ? 4*bp : 0;
            loadx2(xa, emb + (size_t)xrA[rt] * 32);
            loadx2(xb, emb + (size_t)xrB[rt] * 32);
#pragma unroll 1
            for (int mr = 0; mr < 4; ++mr) {
                int m = (w << 2) + mr;
                const u64* wp = sm->Wc2 + m * 48;
                u64 accA = packf2(sm->bc[m], 0.f);
                u64 accB = packf2(sm->bc[m], 0.f);
#pragma unroll
                for (int kk = 0; kk < 16; ++kk) {
                    ffma2(accA, wp[kk], xa[kk]); ffma2(accB, wp[kk], xb[kk]);
                }
#pragma unroll
                for (int kk = 0; kk < 32; ++kk) {
                    ffma2(accA, wp[16 + kk], ha[kk]); ffma2(accB, wp[16 + kk], hb[kk]);
                }
                int row = (bp < 4) ? (bp * 32 + m) : m;
                sm->hidc[row * 65 + e0] = fmaxf(hsum2(accA), 0.f);
                sm->hidc[row * 65 + e1] = fmaxf(hsum2(accB), 0.f);
            }
            __syncthreads();
        }
    }

    // ---- logits + log_softmax (tags split 8 per warp over m) ----
#pragma unroll
    for (int kk = 0; kk < 16; ++kk) {
        xa[kk] = packf2(sm->hidc[(2*kk)*65 + e0], sm->hidc[(2*kk + 1)*65 + e0]);
        xb[kk] = packf2(sm->hidc[(2*kk)*65 + e1], sm->hidc[(2*kk + 1)*65 + e1]);
    }
    float lgA[8], lgB[8], mxA = -1e30f, mxB = -1e30f;
#pragma unroll
    for (int mr = 0; mr < 8; ++mr) {
        int m = (w << 3) + mr;
        const u64* wp = sm->Wt2 + m * 16;
        u64 accA = packf2(sm->bt[m], 0.f);
        u64 accB = packf2(sm->bt[m], 0.f);
#pragma unroll
        for (int kk = 0; kk < 16; ++kk) {
            ffma2(accA, wp[kk], xa[kk]); ffma2(accB, wp[kk], xb[kk]);
        }
        lgA[mr] = hsum2(accA); mxA = fmaxf(mxA, lgA[mr]);
        lgB[mr] = hsum2(accB); mxB = fmaxf(mxB, lgB[mr]);
    }
    float* red = sm->cstg;
    red[w * 64 + e0] = mxA;
    red[w * 64 + e1] = mxB;
    __syncthreads();
    float fmxA = -1e30f, fmxB = -1e30f;
#pragma unroll
    for (int k = 0; k < 8; ++k) {
        fmxA = fmaxf(fmxA, red[k * 64 + e0]);
        fmxB = fmaxf(fmxB, red[k * 64 + e1]);
    }
    float seA = 0.f, seB = 0.f;
#pragma unroll
    for (int mr = 0; mr < 8; ++mr) {
        seA += __expf(lgA[mr] - fmxA);
        seB += __expf(lgB[mr] - fmxB);
    }
    red[2048 + w * 64 + e0] = seA;
    red[2048 + w * 64 + e1] = seB;
    __syncthreads();
    float tseA = 0.f, tseB = 0.f;
#pragma unroll
    for (int k = 0; k < 8; ++k) {
        tseA += red[2048 + k * 64 + e0];
        tseB += red[2048 + k * 64 + e1];
    }
    float lseA = fmxA + logf(tseA);
    float lseB = fmxB + logf(tseB);
    if (actA) {
        float4* o4 = reinterpret_cast<float4*>(out + (size_t)iA * 64 + w * 8);
        float4 v0, v1;
        v0.x = lgA[0]-lseA; v0.y = lgA[1]-lseA; v0.z = lgA[2]-lseA; v0.w = lgA[3]-lseA;
        v1.x = lgA[4]-lseA; v1.y = lgA[5]-lseA; v1.z = lgA[6]-lseA; v1.w = lgA[7]-lseA;
        o4[0] = v0; o4[1] = v1;
    }
    if (actB) {
        float4* o4 = reinterpret_cast<float4*>(out + (size_t)iB * 64 + w * 8);
        float4 v0, v1;
        v0.x = lgB[0]-lseB; v0.y = lgB[1]-lseB; v0.z = lgB[2]-lseB; v0.w = lgB[3]-lseB;
        v1.x = lgB[4]-lseB; v1.y = lgB[5]-lseB; v1.z = lgB[6]-lseB; v1.w = lgB[7]-lseB;
        o4[0] = v0; o4[1] = v1;
    }
}

// ---------------------------------------------------------------------------
extern "C" void kernel_launch(void* const* d_in, const int* in_sizes, int n_in,
                              void* d_out, int out_size)
{
    const int*   x   = (const int*)d_in[0];
    const int*   s   = (const int*)d_in[1];
    const float* emb = (const float*)d_in[2];
    const float* Wih = (const float*)d_in[3];
    const float* Whh = (const float*)d_in[4];
    const float* bih = (const float*)d_in[5];
    const float* bhh = (const float*)d_in[6];
    const float* h0  = (const float*)d_in[7];
    const float* c0  = (const float*)d_in[8];
    const float* Wc  = (const float*)d_in[9];
    const float* bc  = (const float*)d_in[10];
    const float* Wt  = (const float*)d_in[11];
    const float* bt  = (const float*)d_in[12];
    float* out = (float*)d_out;

    int B = in_sizes[1];
    if (B > MAXB) B = MAXB;

    cudaFuncSetAttribute(k_main, cudaFuncAttributeMaxDynamicSharedMemorySize,
                         (int)sizeof(SmemB));

    void* cptr = nullptr;
    cudaGetSymbolAddress(&cptr, g_cnt);
    cudaMemsetAsync(cptr, 0, sizeof(Counters));

    k_compact<<<(B + 255) / 256, 256>>>(s, B);
    int nblk = (B + 63) / 64;
    k_main<<<nblk, 256, sizeof(SmemB)>>>(x, emb, Wih, Whh, bih, bhh,
                                         h0, c0, Wc, bc, Wt, bt, out, B);
}

// round 6
// speedup vs baseline: 6.5519x; 1.0482x over previous
#include <cuda_runtime.h>
#include <cstdint>

// ---------------------------------------------------------------------------
// TrivialTreeTagger: B=32768, 5 tree-LSTM blocks (H=64,E=32).
// last = relu(h3)*(s==4): only s==4 elements (~25%) need LSTM work.
// R6: K-outer gate loop. 64 packed accumulators in regs (no spills),
// operands streamed from shared ([kpair][e] layouts), h double-buffered in
// pair layout, c-state in registers. 4 ffma2 per weight LDS.128 retained.
// ---------------------------------------------------------------------------

#define MAXB 32768

struct Counters { int act; int triv; };
__device__ Counters g_cnt;
__device__ int g_idx[MAXB];
__device__ int g_tidx[MAXB];

typedef unsigned long long u64;

__device__ __forceinline__ float ftanh_(float x) {
    float r; asm("tanh.approx.f32 %0, %1;" : "=f"(r) : "f"(x)); return r;
}
__device__ __forceinline__ float fsig(float x) {
    return fmaf(0.5f, ftanh_(0.5f * x), 0.5f);
}
__device__ __forceinline__ void ffma2(u64& a, u64 b, u64 c) {
    asm("fma.rn.f32x2 %0, %1, %2, %0;" : "+l"(a) : "l"(b), "l"(c));
}
__device__ __forceinline__ u64 packf2(float lo, float hi) {
    u64 r; asm("mov.b64 %0, {%1, %2};" : "=l"(r) : "f"(lo), "f"(hi)); return r;
}
__device__ __forceinline__ float hsum2(u64 v) {
    float lo, hi; asm("mov.b64 {%0, %1}, %2;" : "=f"(lo), "=f"(hi) : "l"(v));
    return lo + hi;
}
__device__ __forceinline__ void load32(float (&dst)[32], const float* __restrict__ src) {
    const float4* p = reinterpret_cast<const float4*>(src);
#pragma unroll
    for (int c = 0; c < 8; ++c) {
        float4 v = p[c];
        dst[4*c] = v.x; dst[4*c+1] = v.y; dst[4*c+2] = v.z; dst[4*c+3] = v.w;
    }
}

// -------------------- kernel 1: compaction ----------------------------------
__global__ void __launch_bounds__(256) k_compact(const int* __restrict__ s, int B)
{
    int i = blockIdx.x * 256 + threadIdx.x;
    bool valid = i < B;
    bool a = valid && (s[i] == 4);
    bool t = valid && !a;
    unsigned ba = __ballot_sync(0xffffffffu, a);
    unsigned bt = __ballot_sync(0xffffffffu, t);
    int lane = threadIdx.x & 31;
    if (a) {
        int leader = __ffs(ba) - 1;
        int pos = 0;
        if (lane == leader) pos = atomicAdd(&g_cnt.act, __popc(ba));
        pos = __shfl_sync(ba, pos, leader);
        g_idx[pos + __popc(ba & ((1u << lane) - 1))] = i;
    } else if (t) {
        int leader = __ffs(bt) - 1;
        int pos = 0;
        if (lane == leader) pos = atomicAdd(&g_cnt.triv, __popc(bt));
        pos = __shfl_sync(bt, pos, leader);
        g_tidx[pos + __popc(bt & ((1u << lane) - 1))] = i;
    }
}

// -------------------- kernel 2: fused main ----------------------------------
struct SmemB {
    u64  W2[64 * 48 * 4];   // [(j*48+kk)*4+gate]: K-pair per gate row (98KB)
    u64  Wc2[32 * 48];      // comb weights K-pairs
    u64  Wt2[64 * 16];      // tag weights K-pairs
    float4 b44[64];
    float4 a044[64];
    float c0s[64];
    float bc[32];
    float bt[64];
    u64  hp[2][32][64];     // h pairs [buf][kpair][e]
    u64  xp[2][16][64];     // x pairs double buffer [buf][kpair][e]
    u64  xroot[16][64];     // root emb pairs; epilogue scratch
    u64  xbig[5][16][64];   // comb outputs per bp, pair layout
};

__global__ void __launch_bounds__(256, 1) k_main(
    const int* __restrict__ x, const float* __restrict__ emb,
    const float* __restrict__ Wih, const float* __restrict__ Whh,
    const float* __restrict__ bih, const float* __restrict__ bhh,
    const float* __restrict__ h0, const float* __restrict__ c0,
    const float* __restrict__ Wc, const float* __restrict__ bcv,
    const float* __restrict__ Wt, const float* __restrict__ btv,
    float* __restrict__ out, int B)
{
    int cnt = g_cnt.act;
    int nl = (cnt + 63) >> 6;
    int tid = threadIdx.x;

    if ((int)blockIdx.x >= nl) {
        // -------------------- trivial path (idle blocks) --------------------
        int tcnt = g_cnt.triv;
        int ntriv = gridDim.x - nl;
        for (int c = blockIdx.x - nl; c * 256 < tcnt; c += ntriv) {
            int ti = c * 256 + tid;
            if (ti >= tcnt) continue;
            int i = g_tidx[ti];
            float r[32];
            load32(r, emb + (size_t)x[i * 16] * 32);
            float cb[32];
#pragma unroll
            for (int m = 0; m < 32; ++m) {
                float acc = bcv[m];
                const float4* w = reinterpret_cast<const float4*>(Wc + m * 96);
#pragma unroll
                for (int k = 0; k < 8; ++k) {
                    float4 wv = w[k];
                    acc = fmaf(wv.x, r[4*k], acc);   acc = fmaf(wv.y, r[4*k+1], acc);
                    acc = fmaf(wv.z, r[4*k+2], acc); acc = fmaf(wv.w, r[4*k+3], acc);
                }
                cb[m] = fmaxf(acc, 0.0f);
            }
            float lg[64], mx = -1e30f;
#pragma unroll
            for (int m = 0; m < 64; ++m) {
                float acc = btv[m];
                const float4* w = reinterpret_cast<const float4*>(Wt + m * 32);
#pragma unroll
                for (int k = 0; k < 8; ++k) {
                    float4 wv = w[k];
                    acc = fmaf(wv.x, cb[4*k], acc);   acc = fmaf(wv.y, cb[4*k+1], acc);
                    acc = fmaf(wv.z, cb[4*k+2], acc); acc = fmaf(wv.w, cb[4*k+3], acc);
                }
                lg[m] = acc; mx = fmaxf(mx, acc);
            }
            float se = 0.0f;
#pragma unroll
            for (int m = 0; m < 64; ++m) se += __expf(lg[m] - mx);
            float lse = mx + logf(se);
            float4* o4 = reinterpret_cast<float4*>(out + (size_t)i * 64);
#pragma unroll
            for (int cc = 0; cc < 16; ++cc) {
                float4 v;
                v.x = lg[4*cc]-lse; v.y = lg[4*cc+1]-lse;
                v.z = lg[4*cc+2]-lse; v.w = lg[4*cc+3]-lse;
                o4[cc] = v;
            }
        }
        return;
    }

    // ------------------------- LSTM path ------------------------------------
    extern __shared__ char smraw[];
    SmemB* sm = reinterpret_cast<SmemB*>(smraw);

    int lane = tid & 31;
    int w = tid >> 5;
    int j0 = w * 8;
    int e0 = lane, e1 = lane + 32;
    int gA = blockIdx.x * 64 + e0, gB = gA + 32;
    bool actA = gA < cnt, actB = gB < cnt;
    int iA = g_idx[actA ? gA : (cnt - 1)];
    int iB = g_idx[actB ? gB : (cnt - 1)];

    // x prefetcher identity: 4 threads per element, pg = 8-float chunk
    int ep = tid & 63, pg = tid >> 6;
    int gp = blockIdx.x * 64 + ep;
    const int* xrP = x + (size_t)g_idx[gp < cnt ? gp : (cnt - 1)] * 16;

    // stage step-0 x into xp[0]
    {
        const ulonglong2* src = reinterpret_cast<const ulonglong2*>(
            emb + (size_t)xrP[0] * 32) + pg * 2;
        ulonglong2 v0 = src[0], v1 = src[1];
        sm->xp[0][pg*4 + 0][ep] = v0.x; sm->xp[0][pg*4 + 1][ep] = v0.y;
        sm->xp[0][pg*4 + 2][ep] = v1.x; sm->xp[0][pg*4 + 3][ep] = v1.y;
    }

    // ---- shared init (weights etc.) ----
    for (int idx = tid; idx < 64 * 48; idx += 256) {
        int j = idx / 48, kk = idx % 48;
#pragma unroll
        for (int gg = 0; gg < 4; ++gg) {
            int row = gg * 64 + j;
            float w0, w1;
            if (kk < 16) { w0 = Wih[row*32 + 2*kk]; w1 = Wih[row*32 + 2*kk + 1]; }
            else { int kh = 2*kk - 32; w0 = Whh[row*64 + kh]; w1 = Whh[row*64 + kh + 1]; }
            sm->W2[idx * 4 + gg] = packf2(w0, w1);
        }
    }
    if (tid < 64) {
        int j = tid;
        float4 bb, aa;
        float* bp_ = reinterpret_cast<float*>(&bb);
        float* ap_ = reinterpret_cast<float*>(&aa);
#pragma unroll
        for (int gg = 0; gg < 4; ++gg) {
            int row = gg * 64 + j;
            float b = bih[row] + bhh[row];
            bp_[gg] = b;
            float a = b;
            for (int k = 0; k < 64; ++k) a = fmaf(Whh[row*64 + k], h0[k], a);
            ap_[gg] = a;
        }
        sm->b44[j] = bb;
        sm->a044[j] = aa;
        sm->c0s[j] = c0[j];
        sm->bt[j] = btv[j];
    }
    for (int idx = tid; idx < 32 * 48; idx += 256) {
        int m = idx / 48, kk = idx % 48;
        sm->Wc2[idx] = packf2(Wc[m*96 + 2*kk], Wc[m*96 + 2*kk + 1]);
    }
    for (int idx = tid; idx < 64 * 16; idx += 256) {
        int m = idx / 16, kk = idx % 16;
        sm->Wt2[idx] = packf2(Wt[m*32 + 2*kk], Wt[m*32 + 2*kk + 1]);
    }
    if (tid < 32) sm->bc[tid] = bcv[tid];
    __syncthreads();

    float cA[8], cB[8];

#pragma unroll 1
    for (int bp = 0; bp < 5; ++bp) {
#pragma unroll 1
        for (int t = 0; t < 4; ++t) {
            int step = 4*bp + t;
            int b = step & 1;

            // prefetch next x (global -> regs; stored after gate loop)
            ulonglong2 p0, p1;
            bool dopf = (step + 1 < 16);
            if (dopf) {
                const ulonglong2* src = reinterpret_cast<const ulonglong2*>(
                    emb + (size_t)xrP[step + 1] * 32) + pg * 2;
                p0 = src[0]; p1 = src[1];
            }
            ulonglong2 r0, r1;
            if (bp == 4 && t == 0) {   // bp4 root = emb[x[0]]
                const ulonglong2* src = reinterpret_cast<const ulonglong2*>(
                    emb + (size_t)xrP[0] * 32) + pg * 2;
                r0 = src[0]; r1 = src[1];
            }

            const u64* ops = (bp < 4) ? &sm->xp[b][0][0] : &sm->xbig[t][0][0];
            const float4* preb = (t == 0) ? sm->a044 : sm->b44;

            u64 aA[8][4], aB[8][4];
#pragma unroll
            for (int r = 0; r < 8; ++r) {
                float4 pv = preb[j0 + r];
                aA[r][0] = packf2(pv.x, 0.f); aA[r][1] = packf2(pv.y, 0.f);
                aA[r][2] = packf2(pv.z, 0.f); aA[r][3] = packf2(pv.w, 0.f);
                aB[r][0] = aA[r][0]; aB[r][1] = aA[r][1];
                aB[r][2] = aA[r][2]; aB[r][3] = aA[r][3];
            }
            // x part (kk 0..15)
#pragma unroll 2
            for (int kk = 0; kk < 16; ++kk) {
                u64 oA = ops[kk*64 + e0], oB = ops[kk*64 + e1];
#pragma unroll
                for (int r = 0; r < 8; ++r) {
                    const ulonglong2* wp = reinterpret_cast<const ulonglong2*>(
                        sm->W2 + ((j0 + r)*48 + kk)*4);
                    ulonglong2 wa = wp[0], wb = wp[1];
                    ffma2(aA[r][0], wa.x, oA); ffma2(aA[r][1], wa.y, oA);
                    ffma2(aA[r][2], wb.x, oA); ffma2(aA[r][3], wb.y, oA);
                    ffma2(aB[r][0], wa.x, oB); ffma2(aB[r][1], wa.y, oB);
                    ffma2(aB[r][2], wb.x, oB); ffma2(aB[r][3], wb.y, oB);
                }
            }
            // h part (kk 0..31), skipped at t==0 (folded into a044)
            if (t > 0) {
                const u64* hrd = &sm->hp[b ^ 1][0][0];
#pragma unroll 2
                for (int kk = 0; kk < 32; ++kk) {
                    u64 oA = hrd[kk*64 + e0], oB = hrd[kk*64 + e1];
#pragma unroll
                    for (int r = 0; r < 8; ++r) {
                        const ulonglong2* wp = reinterpret_cast<const ulonglong2*>(
                            sm->W2 + ((j0 + r)*48 + 16 + kk)*4);
                        ulonglong2 wa = wp[0], wb = wp[1];
                        ffma2(aA[r][0], wa.x, oA); ffma2(aA[r][1], wa.y, oA);
                        ffma2(aA[r][2], wb.x, oA); ffma2(aA[r][3], wb.y, oA);
                        ffma2(aB[r][0], wa.x, oB); ffma2(aB[r][1], wa.y, oB);
                        ffma2(aB[r][2], wb.x, oB); ffma2(aB[r][3], wb.y, oB);
                    }
                }
            }
            // activations + c update + h write (pair layout)
            float* hwf = reinterpret_cast<float*>(&sm->hp[b][0][0]);
#pragma unroll
            for (int r = 0; r < 8; ++r) {
                int j = j0 + r;
                {
                    float ig = fsig(hsum2(aA[r][0])), fg = fsig(hsum2(aA[r][1]));
                    float gv = ftanh_(hsum2(aA[r][2])), og = fsig(hsum2(aA[r][3]));
                    float cp = (t == 0) ? sm->c0s[j] : cA[r];
                    float cc = fmaf(fg, cp, ig * gv);
                    cA[r] = cc;
                    float hn = og * ftanh_(cc);
                    hwf[((j >> 1)*64 + e0)*2 + (j & 1)] = (t == 3) ? fmaxf(hn, 0.f) : hn;
                }
                {
                    float ig = fsig(hsum2(aB[r][0])), fg = fsig(hsum2(aB[r][1]));
                    float gv = ftanh_(hsum2(aB[r][2])), og = fsig(hsum2(aB[r][3]));
                    float cp = (t == 0) ? sm->c0s[j] : cB[r];
                    float cc = fmaf(fg, cp, ig * gv);
                    cB[r] = cc;
                    float hn = og * ftanh_(cc);
                    hwf[((j >> 1)*64 + e1)*2 + (j & 1)] = (t == 3) ? fmaxf(hn, 0.f) : hn;
                }
            }
            // store prefetched next-x
            if (dopf) {
                int nb = (step + 1) & 1;
                sm->xp[nb][pg*4 + 0][ep] = p0.x; sm->xp[nb][pg*4 + 1][ep] = p0.y;
                sm->xp[nb][pg*4 + 2][ep] = p1.x; sm->xp[nb][pg*4 + 3][ep] = p1.y;
            }
            // root staging: bp<4 root token == step-0 child token -> copy xp[0]
            if (t == 0) {
                if (bp < 4) {
                    const u64* s0 = &sm->xp[0][0][0];
                    u64* d0 = &sm->xroot[0][0];
#pragma unroll
                    for (int c = 0; c < 4; ++c) d0[tid*4 + c] = s0[tid*4 + c];
                } else {
                    sm->xroot[pg*4 + 0][ep] = r0.x; sm->xroot[pg*4 + 1][ep] = r0.y;
                    sm->xroot[pg*4 + 2][ep] = r1.x; sm->xroot[pg*4 + 3][ep] = r1.y;
                }
            }
            __syncthreads();
        }

        // ---- comb = relu(Wc @ [root, last] + bc); last in hp[1] ----
        {
            int m0 = w * 4;
            u64 ac[4][2];
#pragma unroll
            for (int mr = 0; mr < 4; ++mr) {
                ac[mr][0] = packf2(sm->bc[m0 + mr], 0.f);
                ac[mr][1] = ac[mr][0];
            }
            const u64* xr_ = &sm->xroot[0][0];
#pragma unroll 2
            for (int kk = 0; kk < 16; ++kk) {
                u64 oA = xr_[kk*64 + e0], oB = xr_[kk*64 + e1];
#pragma unroll
                for (int mr = 0; mr < 4; ++mr) {
                    u64 wv = sm->Wc2[(m0 + mr)*48 + kk];
                    ffma2(ac[mr][0], wv, oA); ffma2(ac[mr][1], wv, oB);
                }
            }
            const u64* hrd = &sm->hp[1][0][0];
#pragma unroll 2
            for (int kk = 0; kk < 32; ++kk) {
                u64 oA = hrd[kk*64 + e0], oB = hrd[kk*64 + e1];
#pragma unroll
                for (int mr = 0; mr < 4; ++mr) {
                    u64 wv = sm->Wc2[(m0 + mr)*48 + 16 + kk];
                    ffma2(ac[mr][0], wv, oA); ffma2(ac[mr][1], wv, oB);
                }
            }
            float* xbf = reinterpret_cast<float*>(&sm->xbig[bp][0][0]);
#pragma unroll
            for (int mr = 0; mr < 4; ++mr) {
                int m = m0 + mr;
                xbf[((m >> 1)*64 + e0)*2 + (m & 1)] = fmaxf(hsum2(ac[mr][0]), 0.f);
                xbf[((m >> 1)*64 + e1)*2 + (m & 1)] = fmaxf(hsum2(ac[mr][1]), 0.f);
            }
            __syncthreads();
        }
    }

    // ---- logits + log_softmax (8 tags per warp) ----
    {
        int m0 = w * 8;
        u64 lA[8], lB[8];
#pragma unroll
        for (int mr = 0; mr < 8; ++mr) {
            lA[mr] = packf2(sm->bt[m0 + mr], 0.f);
            lB[mr] = lA[mr];
        }
        const u64* cbr = &sm->xbig[4][0][0];
#pragma unroll 2
        for (int kk = 0; kk < 16; ++kk) {
            u64 oA = cbr[kk*64 + e0], oB = cbr[kk*64 + e1];
#pragma unroll
            for (int mr = 0; mr < 8; ++mr) {
                u64 wv = sm->Wt2[(m0 + mr)*16 + kk];
                ffma2(lA[mr], wv, oA); ffma2(lB[mr], wv, oB);
            }
        }
        float lgA[8], lgB[8], mxA = -1e30f, mxB = -1e30f;
#pragma unroll
        for (int mr = 0; mr < 8; ++mr) {
            lgA[mr] = hsum2(lA[mr]); mxA = fmaxf(mxA, lgA[mr]);
            lgB[mr] = hsum2(lB[mr]); mxB = fmaxf(mxB, lgB[mr]);
        }
        float* red = reinterpret_cast<float*>(&sm->xroot[0][0]);
        red[w*64 + e0] = mxA;
        red[w*64 + e1] = mxB;
        __syncthreads();
        float fmxA = -1e30f, fmxB = -1e30f;
#pragma unroll
        for (int k = 0; k < 8; ++k) {
            fmxA = fmaxf(fmxA, red[k*64 + e0]);
            fmxB = fmaxf(fmxB, red[k*64 + e1]);
        }
        float seA = 0.f, seB = 0.f;
#pragma unroll
        for (int mr = 0; mr < 8; ++mr) {
            seA += __expf(lgA[mr] - fmxA);
            seB += __expf(lgB[mr] - fmxB);
        }
        red[512 + w*64 + e0] = seA;
        red[512 + w*64 + e1] = seB;
        __syncthreads();
        float tseA = 0.f, tseB = 0.f;
#pragma unroll
        for (int k = 0; k < 8; ++k) {
            tseA += red[512 + k*64 + e0];
            tseB += red[512 + k*64 + e1];
        }
        float lseA = fmxA + logf(tseA);
        float lseB = fmxB + logf(tseB);
        if (actA) {
            float4* o4 = reinterpret_cast<float4*>(out + (size_t)iA * 64 + w * 8);
            float4 v0, v1;
            v0.x = lgA[0]-lseA; v0.y = lgA[1]-lseA; v0.z = lgA[2]-lseA; v0.w = lgA[3]-lseA;
            v1.x = lgA[4]-lseA; v1.y = lgA[5]-lseA; v1.z = lgA[6]-lseA; v1.w = lgA[7]-lseA;
            o4[0] = v0; o4[1] = v1;
        }
        if (actB) {
            float4* o4 = reinterpret_cast<float4*>(out + (size_t)iB * 64 + w * 8);
            float4 v0, v1;
            v0.x = lgB[0]-lseB; v0.y = lgB[1]-lseB; v0.z = lgB[2]-lseB; v0.w = lgB[3]-lseB;
            v1.x = lgB[4]-lseB; v1.y = lgB[5]-lseB; v1.z = lgB[6]-lseB; v1.w = lgB[7]-lseB;
            o4[0] = v0; o4[1] = v1;
        }
    }
}

// ---------------------------------------------------------------------------
extern "C" void kernel_launch(void* const* d_in, const int* in_sizes, int n_in,
                              void* d_out, int out_size)
{
    const int*   x   = (const int*)d_in[0];
    const int*   s   = (const int*)d_in[1];
    const float* emb = (const float*)d_in[2];
    const float* Wih = (const float*)d_in[3];
    const float* Whh = (const float*)d_in[4];
    const float* bih = (const float*)d_in[5];
    const float* bhh = (const float*)d_in[6];
    const float* h0  = (const float*)d_in[7];
    const float* c0  = (const float*)d_in[8];
    const float* Wc  = (const float*)d_in[9];
    const float* bc  = (const float*)d_in[10];
    const float* Wt  = (const float*)d_in[11];
    const float* bt  = (const float*)d_in[12];
    float* out = (float*)d_out;

    int B = in_sizes[1];
    if (B > MAXB) B = MAXB;

    cudaFuncSetAttribute(k_main, cudaFuncAttributeMaxDynamicSharedMemorySize,
                         (int)sizeof(SmemB));

    void* cptr = nullptr;
    cudaGetSymbolAddress(&cptr, g_cnt);
    cudaMemsetAsync(cptr, 0, sizeof(Counters));

    k_compact<<<(B + 255) / 256, 256>>>(s, B);
    int nblk = (B + 63) / 64;
    k_main<<<nblk, 256, sizeof(SmemB)>>>(x, emb, Wih, Whh, bih, bhh,
                                         h0, c0, Wc, bc, Wt, bt, out, B);
}

// round 7
// speedup vs baseline: 7.5005x; 1.1448x over previous
#include <cuda_runtime.h>
#include <cstdint>

// ---------------------------------------------------------------------------
// TrivialTreeTagger: B=32768, 5 tree-LSTM blocks (H=64,E=32).
// last = relu(h3)*(s==4): only s==4 elements (~25%) need LSTM work.
// R7: [kk][j] weight layout (sequential LDS, ~zero addressing ALU) and
// two-pass gates (i,f)/(g,o) -> 32 packed accumulators per pass, register
// headroom for load pipelining. Operands streamed from shared pair layouts.
// ---------------------------------------------------------------------------

#define MAXB 32768

struct Counters { int act; int triv; };
__device__ Counters g_cnt;
__device__ int g_idx[MAXB];
__device__ int g_tidx[MAXB];

typedef unsigned long long u64;

__device__ __forceinline__ float ftanh_(float x) {
    float r; asm("tanh.approx.f32 %0, %1;" : "=f"(r) : "f"(x)); return r;
}
__device__ __forceinline__ float fsig(float x) {
    return fmaf(0.5f, ftanh_(0.5f * x), 0.5f);
}
__device__ __forceinline__ void ffma2(u64& a, u64 b, u64 c) {
    asm("fma.rn.f32x2 %0, %1, %2, %0;" : "+l"(a) : "l"(b), "l"(c));
}
__device__ __forceinline__ u64 packf2(float lo, float hi) {
    u64 r; asm("mov.b64 %0, {%1, %2};" : "=l"(r) : "f"(lo), "f"(hi)); return r;
}
__device__ __forceinline__ float hsum2(u64 v) {
    float lo, hi; asm("mov.b64 {%0, %1}, %2;" : "=f"(lo), "=f"(hi) : "l"(v));
    return lo + hi;
}
__device__ __forceinline__ void load32(float (&dst)[32], const float* __restrict__ src) {
    const float4* p = reinterpret_cast<const float4*>(src);
#pragma unroll
    for (int c = 0; c < 8; ++c) {
        float4 v = p[c];
        dst[4*c] = v.x; dst[4*c+1] = v.y; dst[4*c+2] = v.z; dst[4*c+3] = v.w;
    }
}

// -------------------- kernel 1: compaction ----------------------------------
__global__ void __launch_bounds__(256) k_compact(const int* __restrict__ s, int B)
{
    int i = blockIdx.x * 256 + threadIdx.x;
    bool valid = i < B;
    bool a = valid && (s[i] == 4);
    bool t = valid && !a;
    unsigned ba = __ballot_sync(0xffffffffu, a);
    unsigned bt = __ballot_sync(0xffffffffu, t);
    int lane = threadIdx.x & 31;
    if (a) {
        int leader = __ffs(ba) - 1;
        int pos = 0;
        if (lane == leader) pos = atomicAdd(&g_cnt.act, __popc(ba));
        pos = __shfl_sync(ba, pos, leader);
        g_idx[pos + __popc(ba & ((1u << lane) - 1))] = i;
    } else if (t) {
        int leader = __ffs(bt) - 1;
        int pos = 0;
        if (lane == leader) pos = atomicAdd(&g_cnt.triv, __popc(bt));
        pos = __shfl_sync(bt, pos, leader);
        g_tidx[pos + __popc(bt & ((1u << lane) - 1))] = i;
    }
}

// -------------------- kernel 2: fused main ----------------------------------
struct SmemB {
    ulonglong2 Wif[48][64];  // [kk][j] = (i-gate K-pair, f-gate K-pair)  48KB
    ulonglong2 Wgo[48][64];  // [kk][j] = (g-gate K-pair, o-gate K-pair)  48KB
    u64  Wc2[32 * 48];       // comb weights K-pairs
    u64  Wt2[64 * 16];       // tag weights K-pairs
    float2 bIF[64], bGO[64];
    float2 a0IF[64], a0GO[64];
    float c0s[64];
    float bc[32];
    float bt[64];
    u64  hp[2][32][64];      // h pairs [buf][kpair][e]
    u64  xp[2][16][64];      // x pairs double buffer [buf][kpair][e]
    u64  xroot[16][64];      // root emb pairs; epilogue scratch
    u64  xbig[5][16][64];    // comb outputs per bp, pair layout
};

// One gate-pair pass: accumulate lo/hi gates for 8 rows x 2 elems.
__device__ __forceinline__ void gate_pass(
    const ulonglong2* __restrict__ wbase,   // &W[0][j0]
    const u64* __restrict__ xops, const u64* __restrict__ hops,
    int e0, int e1, bool do_h,
    const float2* __restrict__ pre, int j0,
    float (&glo)[8][2], float (&ghi)[8][2])
{
    u64 aL[8][2], aH[8][2];
#pragma unroll
    for (int r = 0; r < 8; ++r) {
        float2 pv = pre[j0 + r];
        aL[r][0] = packf2(pv.x, 0.f); aL[r][1] = aL[r][0];
        aH[r][0] = packf2(pv.y, 0.f); aH[r][1] = aH[r][0];
    }
#pragma unroll 4
    for (int kk = 0; kk < 16; ++kk) {
        u64 oA = xops[kk*64 + e0], oB = xops[kk*64 + e1];
        const ulonglong2* wp = wbase + kk*64;
#pragma unroll
        for (int r = 0; r < 8; ++r) {
            ulonglong2 wv = wp[r];
            ffma2(aL[r][0], wv.x, oA); ffma2(aH[r][0], wv.y, oA);
            ffma2(aL[r][1], wv.x, oB); ffma2(aH[r][1], wv.y, oB);
        }
    }
    if (do_h) {
#pragma unroll 4
        for (int kk = 0; kk < 32; ++kk) {
            u64 oA = hops[kk*64 + e0], oB = hops[kk*64 + e1];
            const ulonglong2* wp = wbase + (16 + kk)*64;
#pragma unroll
            for (int r = 0; r < 8; ++r) {
                ulonglong2 wv = wp[r];
                ffma2(aL[r][0], wv.x, oA); ffma2(aH[r][0], wv.y, oA);
                ffma2(aL[r][1], wv.x, oB); ffma2(aH[r][1], wv.y, oB);
            }
        }
    }
#pragma unroll
    for (int r = 0; r < 8; ++r) {
        glo[r][0] = hsum2(aL[r][0]); glo[r][1] = hsum2(aL[r][1]);
        ghi[r][0] = hsum2(aH[r][0]); ghi[r][1] = hsum2(aH[r][1]);
    }
}

__global__ void __launch_bounds__(256, 1) k_main(
    const int* __restrict__ x, const float* __restrict__ emb,
    const float* __restrict__ Wih, const float* __restrict__ Whh,
    const float* __restrict__ bih, const float* __restrict__ bhh,
    const float* __restrict__ h0, const float* __restrict__ c0,
    const float* __restrict__ Wc, const float* __restrict__ bcv,
    const float* __restrict__ Wt, const float* __restrict__ btv,
    float* __restrict__ out, int B)
{
    int cnt = g_cnt.act;
    int nl = (cnt + 63) >> 6;
    int tid = threadIdx.x;

    if ((int)blockIdx.x >= nl) {
        // -------------------- trivial path (idle blocks) --------------------
        int tcnt = g_cnt.triv;
        int ntriv = gridDim.x - nl;
        for (int c = blockIdx.x - nl; c * 256 < tcnt; c += ntriv) {
            int ti = c * 256 + tid;
            if (ti >= tcnt) continue;
            int i = g_tidx[ti];
            float r[32];
            load32(r, emb + (size_t)x[i * 16] * 32);
            float cb[32];
#pragma unroll
            for (int m = 0; m < 32; ++m) {
                float acc = bcv[m];
                const float4* w = reinterpret_cast<const float4*>(Wc + m * 96);
#pragma unroll
                for (int k = 0; k < 8; ++k) {
                    float4 wv = w[k];
                    acc = fmaf(wv.x, r[4*k], acc);   acc = fmaf(wv.y, r[4*k+1], acc);
                    acc = fmaf(wv.z, r[4*k+2], acc); acc = fmaf(wv.w, r[4*k+3], acc);
                }
                cb[m] = fmaxf(acc, 0.0f);
            }
            float lg[64], mx = -1e30f;
#pragma unroll
            for (int m = 0; m < 64; ++m) {
                float acc = btv[m];
                const float4* w = reinterpret_cast<const float4*>(Wt + m * 32);
#pragma unroll
                for (int k = 0; k < 8; ++k) {
                    float4 wv = w[k];
                    acc = fmaf(wv.x, cb[4*k], acc);   acc = fmaf(wv.y, cb[4*k+1], acc);
                    acc = fmaf(wv.z, cb[4*k+2], acc); acc = fmaf(wv.w, cb[4*k+3], acc);
                }
                lg[m] = acc; mx = fmaxf(mx, acc);
            }
            float se = 0.0f;
#pragma unroll
            for (int m = 0; m < 64; ++m) se += __expf(lg[m] - mx);
            float lse = mx + logf(se);
            float4* o4 = reinterpret_cast<float4*>(out + (size_t)i * 64);
#pragma unroll
            for (int cc = 0; cc < 16; ++cc) {
                float4 v;
                v.x = lg[4*cc]-lse; v.y = lg[4*cc+1]-lse;
                v.z = lg[4*cc+2]-lse; v.w = lg[4*cc+3]-lse;
                o4[cc] = v;
            }
        }
        return;
    }

    // ------------------------- LSTM path ------------------------------------
    extern __shared__ char smraw[];
    SmemB* sm = reinterpret_cast<SmemB*>(smraw);

    int lane = tid & 31;
    int w = tid >> 5;
    int j0 = w * 8;
    int e0 = lane, e1 = lane + 32;
    int gA = blockIdx.x * 64 + e0, gB = gA + 32;
    bool actA = gA < cnt, actB = gB < cnt;
    int iA = g_idx[actA ? gA : (cnt - 1)];
    int iB = g_idx[actB ? gB : (cnt - 1)];

    // x prefetcher identity: 4 threads per element, pg = 8-float chunk
    int ep = tid & 63, pg = tid >> 6;
    int gp = blockIdx.x * 64 + ep;
    const int* xrP = x + (size_t)g_idx[gp < cnt ? gp : (cnt - 1)] * 16;

    // stage step-0 x into xp[0]
    {
        const ulonglong2* src = reinterpret_cast<const ulonglong2*>(
            emb + (size_t)xrP[0] * 32) + pg * 2;
        ulonglong2 v0 = src[0], v1 = src[1];
        sm->xp[0][pg*4 + 0][ep] = v0.x; sm->xp[0][pg*4 + 1][ep] = v0.y;
        sm->xp[0][pg*4 + 2][ep] = v1.x; sm->xp[0][pg*4 + 3][ep] = v1.y;
    }

    // ---- shared init (weights etc.) ----
    for (int idx = tid; idx < 48 * 64; idx += 256) {
        int kk = idx >> 6, j = idx & 63;
        float wi0, wi1, wf0, wf1, wg0, wg1, wo0, wo1;
        if (kk < 16) {
            int c = 2*kk;
            wi0 = Wih[j*32 + c];          wi1 = Wih[j*32 + c + 1];
            wf0 = Wih[(64 + j)*32 + c];   wf1 = Wih[(64 + j)*32 + c + 1];
            wg0 = Wih[(128 + j)*32 + c];  wg1 = Wih[(128 + j)*32 + c + 1];
            wo0 = Wih[(192 + j)*32 + c];  wo1 = Wih[(192 + j)*32 + c + 1];
        } else {
            int c = 2*kk - 32;
            wi0 = Whh[j*64 + c];          wi1 = Whh[j*64 + c + 1];
            wf0 = Whh[(64 + j)*64 + c];   wf1 = Whh[(64 + j)*64 + c + 1];
            wg0 = Whh[(128 + j)*64 + c];  wg1 = Whh[(128 + j)*64 + c + 1];
            wo0 = Whh[(192 + j)*64 + c];  wo1 = Whh[(192 + j)*64 + c + 1];
        }
        ulonglong2 vif, vgo;
        vif.x = packf2(wi0, wi1); vif.y = packf2(wf0, wf1);
        vgo.x = packf2(wg0, wg1); vgo.y = packf2(wo0, wo1);
        sm->Wif[kk][j] = vif;
        sm->Wgo[kk][j] = vgo;
    }
    if (tid < 64) {
        int j = tid;
        float bi = bih[j] + bhh[j];
        float bf = bih[64 + j] + bhh[64 + j];
        float bg = bih[128 + j] + bhh[128 + j];
        float bo = bih[192 + j] + bhh[192 + j];
        float ai = bi, af = bf, ag = bg, ao = bo;
        for (int k = 0; k < 64; ++k) {
            float hk = h0[k];
            ai = fmaf(Whh[j*64 + k], hk, ai);
            af = fmaf(Whh[(64 + j)*64 + k], hk, af);
            ag = fmaf(Whh[(128 + j)*64 + k], hk, ag);
            ao = fmaf(Whh[(192 + j)*64 + k], hk, ao);
        }
        sm->bIF[j]  = make_float2(bi, bf);
        sm->bGO[j]  = make_float2(bg, bo);
        sm->a0IF[j] = make_float2(ai, af);
        sm->a0GO[j] = make_float2(ag, ao);
        sm->c0s[j] = c0[j];
        sm->bt[j] = btv[j];
    }
    for (int idx = tid; idx < 32 * 48; idx += 256) {
        int m = idx / 48, kk = idx % 48;
        sm->Wc2[idx] = packf2(Wc[m*96 + 2*kk], Wc[m*96 + 2*kk + 1]);
    }
    for (int idx = tid; idx < 64 * 16; idx += 256) {
        int m = idx / 16, kk = idx % 16;
        sm->Wt2[idx] = packf2(Wt[m*32 + 2*kk], Wt[m*32 + 2*kk + 1]);
    }
    if (tid < 32) sm->bc[tid] = bcv[tid];
    __syncthreads();

    float cA[8], cB[8];

#pragma unroll 1
    for (int bp = 0; bp < 5; ++bp) {
#pragma unroll 1
        for (int t = 0; t < 4; ++t) {
            int step = 4*bp + t;
            int b = step & 1;

            // prefetch next x (global -> regs; stored after gate passes)
            ulonglong2 p0, p1;
            bool dopf = (step + 1 < 16);
            if (dopf) {
                const ulonglong2* src = reinterpret_cast<const ulonglong2*>(
                    emb + (size_t)xrP[step + 1] * 32) + pg * 2;
                p0 = src[0]; p1 = src[1];
            }
            ulonglong2 r0, r1;
            if (bp == 4 && t == 0) {   // bp4 root = emb[x[0]]
                const ulonglong2* src = reinterpret_cast<const ulonglong2*>(
                    emb + (size_t)xrP[0] * 32) + pg * 2;
                r0 = src[0]; r1 = src[1];
            }

            const u64* ops = (bp < 4) ? &sm->xp[b][0][0] : &sm->xbig[t][0][0];
            const u64* hrd = &sm->hp[b ^ 1][0][0];

            float gi[8][2], gf[8][2], gg[8][2], go[8][2];
            gate_pass(&sm->Wif[0][j0], ops, hrd, e0, e1, t > 0,
                      (t == 0) ? sm->a0IF : sm->bIF, j0, gi, gf);
            gate_pass(&sm->Wgo[0][j0], ops, hrd, e0, e1, t > 0,
                      (t == 0) ? sm->a0GO : sm->bGO, j0, gg, go);

            // activations + c update + h write (pair layout)
            float* hwf = reinterpret_cast<float*>(&sm->hp[b][0][0]);
#pragma unroll
            for (int r = 0; r < 8; ++r) {
                int j = j0 + r;
                {
                    float iv = fsig(gi[r][0]), fv = fsig(gf[r][0]);
                    float gv = ftanh_(gg[r][0]), ov = fsig(go[r][0]);
                    float cp = (t == 0) ? sm->c0s[j] : cA[r];
                    float cc = fmaf(fv, cp, iv * gv);
                    cA[r] = cc;
                    float hn = ov * ftanh_(cc);
                    hwf[((j >> 1)*64 + e0)*2 + (j & 1)] = (t == 3) ? fmaxf(hn, 0.f) : hn;
                }
                {
                    float iv = fsig(gi[r][1]), fv = fsig(gf[r][1]);
                    float gv = ftanh_(gg[r][1]), ov = fsig(go[r][1]);
                    float cp = (t == 0) ? sm->c0s[j] : cB[r];
                    float cc = fmaf(fv, cp, iv * gv);
                    cB[r] = cc;
                    float hn = ov * ftanh_(cc);
                    hwf[((j >> 1)*64 + e1)*2 + (j & 1)] = (t == 3) ? fmaxf(hn, 0.f) : hn;
                }
            }
            // store prefetched next-x
            if (dopf) {
                int nb = (step + 1) & 1;
                sm->xp[nb][pg*4 + 0][ep] = p0.x; sm->xp[nb][pg*4 + 1][ep] = p0.y;
                sm->xp[nb][pg*4 + 2][ep] = p1.x; sm->xp[nb][pg*4 + 3][ep] = p1.y;
            }
            // root staging: bp<4 root token == step-0 child token -> copy xp[0]
            if (t == 0) {
                if (bp < 4) {
                    const u64* s0 = &sm->xp[0][0][0];
                    u64* d0 = &sm->xroot[0][0];
#pragma unroll
                    for (int c = 0; c < 4; ++c) d0[tid*4 + c] = s0[tid*4 + c];
                } else {
                    sm->xroot[pg*4 + 0][ep] = r0.x; sm->xroot[pg*4 + 1][ep] = r0.y;
                    sm->xroot[pg*4 + 2][ep] = r1.x; sm->xroot[pg*4 + 3][ep] = r1.y;
                }
            }
            __syncthreads();
        }

        // ---- comb = relu(Wc @ [root, last] + bc); last in hp[1] ----
        {
            int m0 = w * 4;
            u64 ac[4][2];
#pragma unroll
            for (int mr = 0; mr < 4; ++mr) {
                ac[mr][0] = packf2(sm->bc[m0 + mr], 0.f);
                ac[mr][1] = ac[mr][0];
            }
            const u64* xr_ = &sm->xroot[0][0];
#pragma unroll 4
            for (int kk = 0; kk < 16; ++kk) {
                u64 oA = xr_[kk*64 + e0], oB = xr_[kk*64 + e1];
#pragma unroll
                for (int mr = 0; mr < 4; ++mr) {
                    u64 wv = sm->Wc2[(m0 + mr)*48 + kk];
                    ffma2(ac[mr][0], wv, oA); ffma2(ac[mr][1], wv, oB);
                }
            }
            const u64* hrd = &sm->hp[1][0][0];
#pragma unroll 4
            for (int kk = 0; kk < 32; ++kk) {
                u64 oA = hrd[kk*64 + e0], oB = hrd[kk*64 + e1];
#pragma unroll
                for (int mr = 0; mr < 4; ++mr) {
                    u64 wv = sm->Wc2[(m0 + mr)*48 + 16 + kk];
                    ffma2(ac[mr][0], wv, oA); ffma2(ac[mr][1], wv, oB);
                }
            }
            float* xbf = reinterpret_cast<float*>(&sm->xbig[bp][0][0]);
#pragma unroll
            for (int mr = 0; mr < 4; ++mr) {
                int m = m0 + mr;
                xbf[((m >> 1)*64 + e0)*2 + (m & 1)] = fmaxf(hsum2(ac[mr][0]), 0.f);
                xbf[((m >> 1)*64 + e1)*2 + (m & 1)] = fmaxf(hsum2(ac[mr][1]), 0.f);
            }
            __syncthreads();
        }
    }

    // ---- logits + log_softmax (8 tags per warp) ----
    {
        int m0 = w * 8;
        u64 lA[8], lB[8];
#pragma unroll
        for (int mr = 0; mr < 8; ++mr) {
            lA[mr] = packf2(sm->bt[m0 + mr], 0.f);
            lB[mr] = lA[mr];
        }
        const u64* cbr = &sm->xbig[4][0][0];
#pragma unroll 4
        for (int kk = 0; kk < 16; ++kk) {
            u64 oA = cbr[kk*64 + e0], oB = cbr[kk*64 + e1];
#pragma unroll
            for (int mr = 0; mr < 8; ++mr) {
                u64 wv = sm->Wt2[(m0 + mr)*16 + kk];
                ffma2(lA[mr], wv, oA); ffma2(lB[mr], wv, oB);
            }
        }
        float lgA[8], lgB[8], mxA = -1e30f, mxB = -1e30f;
#pragma unroll
        for (int mr = 0; mr < 8; ++mr) {
            lgA[mr] = hsum2(lA[mr]); mxA = fmaxf(mxA, lgA[mr]);
            lgB[mr] = hsum2(lB[mr]); mxB = fmaxf(mxB, lgB[mr]);
        }
        float* red = reinterpret_cast<float*>(&sm->xroot[0][0]);
        red[w*64 + e0] = mxA;
        red[w*64 + e1] = mxB;
        __syncthreads();
        float fmxA = -1e30f, fmxB = -1e30f;
#pragma unroll
        for (int k = 0; k < 8; ++k) {
            fmxA = fmaxf(fmxA, red[k*64 + e0]);
            fmxB = fmaxf(fmxB, red[k*64 + e1]);
        }
        float seA = 0.f, seB = 0.f;
#pragma unroll
        for (int mr = 0; mr < 8; ++mr) {
            seA += __expf(lgA[mr] - fmxA);
            seB += __expf(lgB[mr] - fmxB);
        }
        red[512 + w*64 + e0] = seA;
        red[512 + w*64 + e1] = seB;
        __syncthreads();
        float tseA = 0.f, tseB = 0.f;
#pragma unroll
        for (int k = 0; k < 8; ++k) {
            tseA += red[512 + k*64 + e0];
            tseB += red[512 + k*64 + e1];
        }
        float lseA = fmxA + logf(tseA);
        float lseB = fmxB + logf(tseB);
        if (actA) {
            float4* o4 = reinterpret_cast<float4*>(out + (size_t)iA * 64 + w * 8);
            float4 v0, v1;
            v0.x = lgA[0]-lseA; v0.y = lgA[1]-lseA; v0.z = lgA[2]-lseA; v0.w = lgA[3]-lseA;
            v1.x = lgA[4]-lseA; v1.y = lgA[5]-lseA; v1.z = lgA[6]-lseA; v1.w = lgA[7]-lseA;
            o4[0] = v0; o4[1] = v1;
        }
        if (actB) {
            float4* o4 = reinterpret_cast<float4*>(out + (size_t)iB * 64 + w * 8);
            float4 v0, v1;
            v0.x = lgB[0]-lseB; v0.y = lgB[1]-lseB; v0.z = lgB[2]-lseB; v0.w = lgB[3]-lseB;
            v1.x = lgB[4]-lseB; v1.y = lgB[5]-lseB; v1.z = lgB[6]-lseB; v1.w = lgB[7]-lseB;
            o4[0] = v0; o4[1] = v1;
        }
    }
}

// ---------------------------------------------------------------------------
extern "C" void kernel_launch(void* const* d_in, const int* in_sizes, int n_in,
                              void* d_out, int out_size)
{
    const int*   x   = (const int*)d_in[0];
    const int*   s   = (const int*)d_in[1];
    const float* emb = (const float*)d_in[2];
    const float* Wih = (const float*)d_in[3];
    const float* Whh = (const float*)d_in[4];
    const float* bih = (const float*)d_in[5];
    const float* bhh = (const float*)d_in[6];
    const float* h0  = (const float*)d_in[7];
    const float* c0  = (const float*)d_in[8];
    const float* Wc  = (const float*)d_in[9];
    const float* bc  = (const float*)d_in[10];
    const float* Wt  = (const float*)d_in[11];
    const float* bt  = (const float*)d_in[12];
    float* out = (float*)d_out;

    int B = in_sizes[1];
    if (B > MAXB) B = MAXB;

    cudaFuncSetAttribute(k_main, cudaFuncAttributeMaxDynamicSharedMemorySize,
                         (int)sizeof(SmemB));

    void* cptr = nullptr;
    cudaGetSymbolAddress(&cptr, g_cnt);
    cudaMemsetAsync(cptr, 0, sizeof(Counters));

    k_compact<<<(B + 255) / 256, 256>>>(s, B);
    int nblk = (B + 63) / 64;
    k_main<<<nblk, 256, sizeof(SmemB)>>>(x, emb, Wih, Whh, bih, bhh,
                                         h0, c0, Wc, bc, Wt, bt, out, B);
}